// round 1
// baseline (speedup 1.0000x reference)
#include <cuda_runtime.h>
#include <cuda_bf16.h>
#include <math.h>

#define B_   16
#define S_   512
#define H_   768
#define NH_  12
#define L_   6
#define FF_  3072
#define DH_  64
#define LAB_ 10

// ---------------- scratch (device globals; no allocations allowed) ----------
__device__ float g_x  [(size_t)B_*S_*H_];
__device__ float g_q  [(size_t)B_*S_*H_];
__device__ float g_k  [(size_t)B_*S_*H_];
__device__ float g_v  [(size_t)B_*S_*H_];
__device__ float g_ctx[(size_t)B_*S_*H_];
__device__ float g_tmp[(size_t)B_*S_*H_];
__device__ float g_ff [(size_t)B_*S_*FF_];
__device__ float g_sc [(size_t)B_*NH_*S_*S_];
__device__ float g_hidden[(size_t)B_*H_];
__device__ float g_logits[(size_t)B_*LAB_];

// ---------------- block reductions ----------------
__device__ __forceinline__ float block_reduce_sum(float v, float* sbuf) {
    __syncthreads();
    #pragma unroll
    for (int o = 16; o; o >>= 1) v += __shfl_down_sync(0xffffffffu, v, o);
    int lane = threadIdx.x & 31, w = threadIdx.x >> 5;
    if (lane == 0) sbuf[w] = v;
    __syncthreads();
    if (w == 0) {
        int nw = (blockDim.x + 31) >> 5;
        v = (lane < nw) ? sbuf[lane] : 0.f;
        #pragma unroll
        for (int o = 16; o; o >>= 1) v += __shfl_down_sync(0xffffffffu, v, o);
        if (lane == 0) sbuf[0] = v;
    }
    __syncthreads();
    return sbuf[0];
}

__device__ __forceinline__ float block_reduce_max(float v, float* sbuf) {
    __syncthreads();
    #pragma unroll
    for (int o = 16; o; o >>= 1) v = fmaxf(v, __shfl_down_sync(0xffffffffu, v, o));
    int lane = threadIdx.x & 31, w = threadIdx.x >> 5;
    if (lane == 0) sbuf[w] = v;
    __syncthreads();
    if (w == 0) {
        int nw = (blockDim.x + 31) >> 5;
        v = (lane < nw) ? sbuf[lane] : -3.4e38f;
        #pragma unroll
        for (int o = 16; o; o >>= 1) v = fmaxf(v, __shfl_down_sync(0xffffffffu, v, o));
        if (lane == 0) sbuf[0] = v;
    }
    __syncthreads();
    return sbuf[0];
}

// ---------------- embedding + LN + selection ----------------
__global__ void embed_kernel(const int* __restrict__ src, const int* __restrict__ seg,
                             const int* __restrict__ tib,
                             const float* __restrict__ we, const float* __restrict__ pe,
                             const float* __restrict__ se,
                             const float* __restrict__ g, const float* __restrict__ bta,
                             const float* __restrict__ sel, float* __restrict__ x)
{
    int t = blockIdx.x;            // token index 0..B*S-1
    int s = t % S_;
    __shared__ float e[H_];
    __shared__ float sbuf[32];
    int w = src[t], sg = seg[t];
    const float* wr = we + (size_t)w * H_;
    const float* pr = pe + (size_t)s * H_;
    const float* sr = se + (size_t)sg * H_;
    float lsum = 0.f, lsq = 0.f;
    for (int j = threadIdx.x; j < H_; j += blockDim.x) {
        float val = wr[j] + pr[j] + sr[j];
        e[j] = val; lsum += val; lsq += val * val;
    }
    float tot = block_reduce_sum(lsum, sbuf);
    float totsq = block_reduce_sum(lsq, sbuf);
    float mean = tot / H_;
    float var  = totsq / H_ - mean * mean;
    float inv  = rsqrtf(var + 1e-5f);
    float f = sel[tib[t]];
    float* xo = x + (size_t)t * H_;
    for (int j = threadIdx.x; j < H_; j += blockDim.x)
        xo[j] = ((e[j] - mean) * inv * g[j] + bta[j]) * f;
}

// ---------------- residual add + LN (in place on x) ----------------
__global__ void add_ln_kernel(float* __restrict__ x, const float* __restrict__ t,
                              const float* __restrict__ g, const float* __restrict__ bta)
{
    int row = blockIdx.x;
    __shared__ float e[H_];
    __shared__ float sbuf[32];
    float* xr = x + (size_t)row * H_;
    const float* tr = t + (size_t)row * H_;
    float lsum = 0.f, lsq = 0.f;
    for (int j = threadIdx.x; j < H_; j += blockDim.x) {
        float val = xr[j] + tr[j];
        e[j] = val; lsum += val; lsq += val * val;
    }
    float tot = block_reduce_sum(lsum, sbuf);
    float totsq = block_reduce_sum(lsq, sbuf);
    float mean = tot / H_;
    float var  = totsq / H_ - mean * mean;
    float inv  = rsqrtf(var + 1e-5f);
    for (int j = threadIdx.x; j < H_; j += blockDim.x)
        xr[j] = (e[j] - mean) * inv * g[j] + bta[j];
}

// ---------------- masked softmax over score rows ----------------
__global__ void softmax_kernel(float* __restrict__ sc, const int* __restrict__ seg)
{
    long row = blockIdx.x;                    // 0 .. B*NH*S-1
    int b = (int)(row / ((long)NH_ * S_));
    float* p = sc + row * S_;
    const int* segb = seg + (size_t)b * S_;
    __shared__ float sbuf[32];

    float vals[2];
    float lmax = -3.4e38f;
    #pragma unroll
    for (int r = 0; r < 2; r++) {
        int k = threadIdx.x + r * 256;
        float vv = p[k] + (segb[k] > 0 ? 0.f : -1e9f);
        vals[r] = vv;
        lmax = fmaxf(lmax, vv);
    }
    float mx = block_reduce_max(lmax, sbuf);
    float lsum = 0.f;
    #pragma unroll
    for (int r = 0; r < 2; r++) {
        vals[r] = __expf(vals[r] - mx);
        lsum += vals[r];
    }
    float sum = block_reduce_sum(lsum, sbuf);
    float rinv = 1.f / sum;
    #pragma unroll
    for (int r = 0; r < 2; r++) {
        int k = threadIdx.x + r * 256;
        p[k] = vals[r] * rinv;
    }
}

// ---------------- generic (batched) tiled GEMM ----------------
// C = act(alpha * A@B(^T) + bias), batch index z decomposed as (b,h) with
// per-batch pointer offsets b*sXb + h*sXh.
#define BM 64
#define BN 64
#define BK 16
#define TM 4
#define TN 4

template<int ACT> // 0 none, 1 gelu(tanh), 2 tanh
__global__ void gemm_kernel(const float* __restrict__ A, const float* __restrict__ Bm,
                            const float* __restrict__ bias, float* __restrict__ C,
                            int M, int N, int K, int lda, int ldb, int ldc,
                            long sAb, long sAh, long sBb, long sBh, long sCb, long sCh,
                            int nh, int transB, float alpha)
{
    int bh = blockIdx.z;
    int b = bh / nh, h = bh % nh;
    A  += (long)b * sAb + (long)h * sAh;
    Bm += (long)b * sBb + (long)h * sBh;
    C  += (long)b * sCb + (long)h * sCh;

    __shared__ float As[BK][BM + 1];
    __shared__ float Bs[BK][BN + 1];

    int m0 = blockIdx.y * BM;
    int n0 = blockIdx.x * BN;
    int tid = threadIdx.x;
    int tx = tid & 15, ty = tid >> 4;

    float acc[TM][TN] = {};

    for (int k0 = 0; k0 < K; k0 += BK) {
        #pragma unroll
        for (int i = tid; i < BM * BK; i += 256) {
            int m = i >> 4, k = i & 15;
            int gm = m0 + m, gk = k0 + k;
            As[k][m] = (gm < M && gk < K) ? A[(long)gm * lda + gk] : 0.f;
        }
        if (!transB) {
            #pragma unroll
            for (int i = tid; i < BK * BN; i += 256) {
                int k = i >> 6, n = i & 63;
                int gk = k0 + k, gn = n0 + n;
                Bs[k][n] = (gk < K && gn < N) ? Bm[(long)gk * ldb + gn] : 0.f;
            }
        } else {
            #pragma unroll
            for (int i = tid; i < BK * BN; i += 256) {
                int n = i >> 4, k = i & 15;
                int gk = k0 + k, gn = n0 + n;
                Bs[k][n] = (gk < K && gn < N) ? Bm[(long)gn * ldb + gk] : 0.f;
            }
        }
        __syncthreads();
        #pragma unroll
        for (int k = 0; k < BK; k++) {
            float a[TM], bb[TN];
            #pragma unroll
            for (int i = 0; i < TM; i++) a[i] = As[k][ty * TM + i];
            #pragma unroll
            for (int j = 0; j < TN; j++) bb[j] = Bs[k][tx * TN + j];
            #pragma unroll
            for (int i = 0; i < TM; i++)
                #pragma unroll
                for (int j = 0; j < TN; j++)
                    acc[i][j] = fmaf(a[i], bb[j], acc[i][j]);
        }
        __syncthreads();
    }

    #pragma unroll
    for (int i = 0; i < TM; i++) {
        int gm = m0 + ty * TM + i;
        if (gm >= M) continue;
        #pragma unroll
        for (int j = 0; j < TN; j++) {
            int gn = n0 + tx * TN + j;
            if (gn >= N) continue;
            float v = acc[i][j] * alpha;
            if (bias) v += bias[gn];
            if (ACT == 1) {
                float c = v * v * v;
                v = 0.5f * v * (1.f + tanhf(0.7978845608028654f * (v + 0.044715f * c)));
            } else if (ACT == 2) {
                v = tanhf(v);
            }
            C[(long)gm * ldc + gn] = v;
        }
    }
}

// ---------------- log-softmax + NLL loss + output write ----------------
__global__ void loss_kernel(const float* __restrict__ logits, const int* __restrict__ tgt,
                            float* __restrict__ out, int out_size)
{
    int lane = threadIdx.x;
    float lp = 0.f;
    if (lane < B_) {
        const float* row = logits + lane * LAB_;
        float mx = row[0];
        #pragma unroll
        for (int j = 1; j < LAB_; j++) mx = fmaxf(mx, row[j]);
        float s = 0.f;
        #pragma unroll
        for (int j = 0; j < LAB_; j++) s += expf(row[j] - mx);
        lp = row[tgt[lane]] - mx - logf(s);
    }
    #pragma unroll
    for (int o = 16; o; o >>= 1) lp += __shfl_down_sync(0xffffffffu, lp, o);
    int ofs = (out_size > B_ * LAB_) ? 1 : 0;
    if (lane == 0 && ofs) out[0] = -lp / (float)B_;
    for (int i = lane; i < B_ * LAB_; i += 32) out[ofs + i] = logits[i];
}

// ---------------- host launch ----------------
extern "C" void kernel_launch(void* const* d_in, const int* in_sizes, int n_in,
                              void* d_out, int out_size)
{
    const int*   src  = (const int*)d_in[0];
    const int*   seg  = (const int*)d_in[1];
    const int*   tgt  = (const int*)d_in[2];
    const int*   tib  = (const int*)d_in[3];
    const float* we   = (const float*)d_in[4];
    const float* pe   = (const float*)d_in[5];
    const float* se   = (const float*)d_in[6];
    const float* elng = (const float*)d_in[7];
    const float* elnb = (const float*)d_in[8];
    const float* Wq   = (const float*)d_in[9];
    const float* bq   = (const float*)d_in[10];
    const float* Wk   = (const float*)d_in[11];
    const float* bk   = (const float*)d_in[12];
    const float* Wv   = (const float*)d_in[13];
    const float* bv   = (const float*)d_in[14];
    const float* Wo   = (const float*)d_in[15];
    const float* bo   = (const float*)d_in[16];
    const float* ln1g = (const float*)d_in[17];
    const float* ln1b = (const float*)d_in[18];
    const float* Wf1  = (const float*)d_in[19];
    const float* bf1  = (const float*)d_in[20];
    const float* Wf2  = (const float*)d_in[21];
    const float* bf2  = (const float*)d_in[22];
    const float* ln2g = (const float*)d_in[23];
    const float* ln2b = (const float*)d_in[24];
    const float* Wp1  = (const float*)d_in[25];
    const float* bp1  = (const float*)d_in[26];
    const float* Wp2  = (const float*)d_in[27];
    const float* bp2  = (const float*)d_in[28];
    const float* sel  = (const float*)d_in[29];
    (void)in_sizes; (void)n_in;

    float *x, *q, *k, *v, *ctx, *tmp, *ff, *sc, *hidden, *logits;
    cudaGetSymbolAddress((void**)&x,     g_x);
    cudaGetSymbolAddress((void**)&q,     g_q);
    cudaGetSymbolAddress((void**)&k,     g_k);
    cudaGetSymbolAddress((void**)&v,     g_v);
    cudaGetSymbolAddress((void**)&ctx,   g_ctx);
    cudaGetSymbolAddress((void**)&tmp,   g_tmp);
    cudaGetSymbolAddress((void**)&ff,    g_ff);
    cudaGetSymbolAddress((void**)&sc,    g_sc);
    cudaGetSymbolAddress((void**)&hidden,g_hidden);
    cudaGetSymbolAddress((void**)&logits,g_logits);

    const int Mtok = B_ * S_;                    // 8192
    dim3 blk(256);
    dim3 gH ((H_  + BN - 1) / BN, (Mtok + BM - 1) / BM, 1);   // (12,128,1)
    dim3 gFF((FF_ + BN - 1) / BN, (Mtok + BM - 1) / BM, 1);   // (48,128,1)

    embed_kernel<<<Mtok, 256>>>(src, seg, tib, we, pe, se, elng, elnb, sel, x);

    const long sQKVb = (long)S_ * H_;   // token-batch stride over b
    const long sHead = DH_;             // head column offset
    const long sScB  = (long)NH_ * S_ * S_;
    const long sScH  = (long)S_ * S_;

    for (int l = 0; l < L_; l++) {
        const float* wq = Wq + (size_t)l * H_ * H_;
        const float* wk = Wk + (size_t)l * H_ * H_;
        const float* wv = Wv + (size_t)l * H_ * H_;
        const float* wo = Wo + (size_t)l * H_ * H_;
        const float* wf1 = Wf1 + (size_t)l * H_ * FF_;
        const float* wf2 = Wf2 + (size_t)l * FF_ * H_;

        gemm_kernel<0><<<gH, blk>>>(x, wq, bq + l * H_, q, Mtok, H_, H_, H_, H_, H_,
                                    0,0,0,0,0,0, 1, 0, 1.f);
        gemm_kernel<0><<<gH, blk>>>(x, wk, bk + l * H_, k, Mtok, H_, H_, H_, H_, H_,
                                    0,0,0,0,0,0, 1, 0, 1.f);
        gemm_kernel<0><<<gH, blk>>>(x, wv, bv + l * H_, v, Mtok, H_, H_, H_, H_, H_,
                                    0,0,0,0,0,0, 1, 0, 1.f);

        // scores = q @ k^T / 8  per (b,h):  M=S, N=S, K=DH
        dim3 gScore(S_ / BN, S_ / BM, B_ * NH_);
        gemm_kernel<0><<<gScore, blk>>>(q, k, nullptr, sc, S_, S_, DH_, H_, H_, S_,
                                        sQKVb, sHead, sQKVb, sHead, sScB, sScH,
                                        NH_, 1, 0.125f);

        softmax_kernel<<<B_ * NH_ * S_, 256>>>(sc, seg);

        // ctx = probs @ v  per (b,h): M=S, N=DH, K=S ; write into (B,S,H) layout
        dim3 gCtx(1, S_ / BM, B_ * NH_);
        gemm_kernel<0><<<gCtx, blk>>>(sc, v, nullptr, ctx, S_, DH_, S_, S_, H_, H_,
                                      sScB, sScH, sQKVb, sHead, sQKVb, sHead,
                                      NH_, 0, 1.f);

        gemm_kernel<0><<<gH, blk>>>(ctx, wo, bo + l * H_, tmp, Mtok, H_, H_, H_, H_, H_,
                                    0,0,0,0,0,0, 1, 0, 1.f);
        add_ln_kernel<<<Mtok, 256>>>(x, tmp, ln1g + l * H_, ln1b + l * H_);

        gemm_kernel<1><<<gFF, blk>>>(x, wf1, bf1 + l * FF_, ff, Mtok, FF_, H_, H_, FF_, FF_,
                                     0,0,0,0,0,0, 1, 0, 1.f);
        gemm_kernel<0><<<gH, blk>>>(ff, wf2, bf2 + l * H_, tmp, Mtok, H_, FF_, FF_, H_, H_,
                                    0,0,0,0,0,0, 1, 0, 1.f);
        add_ln_kernel<<<Mtok, 256>>>(x, tmp, ln2g + l * H_, ln2b + l * H_);
    }

    // pooled rows are x[b*S, :]  -> use lda = S*H to stride over batch rows
    dim3 gPool((H_ + BN - 1) / BN, 1, 1);
    gemm_kernel<2><<<gPool, blk>>>(x, Wp1, bp1, hidden, B_, H_, H_,
                                   S_ * H_, H_, H_, 0,0,0,0,0,0, 1, 0, 1.f);
    dim3 gCls(1, 1, 1);
    gemm_kernel<0><<<gCls, blk>>>(hidden, Wp2, bp2, logits, B_, LAB_, H_,
                                  H_, LAB_, LAB_, 0,0,0,0,0,0, 1, 0, 1.f);

    loss_kernel<<<1, 32>>>(logits, tgt, (float*)d_out, out_size);
}

// round 2
// speedup vs baseline: 5.5954x; 5.5954x over previous
#include <cuda_runtime.h>
#include <cuda_bf16.h>
#include <math.h>
#include <stdint.h>

#define B_   16
#define S_   512
#define H_   768
#define NH_  12
#define L_   6
#define FF_  3072
#define DH_  64
#define LAB_ 10

// ---------------- scratch (device globals; no allocations allowed) ----------
__device__ float g_x  [(size_t)B_*S_*H_];
__device__ float g_q  [(size_t)B_*S_*H_];
__device__ float g_k  [(size_t)B_*S_*H_];
__device__ float g_v  [(size_t)B_*S_*H_];
__device__ float g_ctx[(size_t)B_*S_*H_];
__device__ float g_tmp[(size_t)B_*S_*H_];
__device__ float g_ff [(size_t)B_*S_*FF_];
__device__ float g_sc [(size_t)B_*NH_*S_*S_];
__device__ float g_hidden[(size_t)B_*H_];
__device__ float g_logits[(size_t)B_*LAB_];

// ---------------- small helpers ----------------
__device__ __forceinline__ uint32_t f2tf32(float f) {
    uint32_t u;
    asm("cvt.rna.tf32.f32 %0, %1;" : "=r"(u) : "f"(f));
    return u;
}

__device__ __forceinline__ void cp16(void* s, const void* g) {
    uint32_t sa = (uint32_t)__cvta_generic_to_shared(s);
    asm volatile("cp.async.ca.shared.global [%0], [%1], 16;\n" :: "r"(sa), "l"(g));
}

__device__ __forceinline__ void mma_tf32(float* c, const uint32_t* a, const uint32_t* b) {
    asm volatile(
        "mma.sync.aligned.m16n8k8.row.col.f32.tf32.tf32.f32 "
        "{%0,%1,%2,%3}, {%4,%5,%6,%7}, {%8,%9}, {%0,%1,%2,%3};\n"
        : "+f"(c[0]), "+f"(c[1]), "+f"(c[2]), "+f"(c[3])
        : "r"(a[0]), "r"(a[1]), "r"(a[2]), "r"(a[3]), "r"(b[0]), "r"(b[1]));
}

__device__ __forceinline__ float gelu_tanh(float v) {
    float c = v * v * v;
    return 0.5f * v * (1.f + tanhf(0.7978845608028654f * (v + 0.044715f * c)));
}

// ---------------- block reductions ----------------
__device__ __forceinline__ float block_reduce_sum(float v, float* sbuf) {
    __syncthreads();
    #pragma unroll
    for (int o = 16; o; o >>= 1) v += __shfl_down_sync(0xffffffffu, v, o);
    int lane = threadIdx.x & 31, w = threadIdx.x >> 5;
    if (lane == 0) sbuf[w] = v;
    __syncthreads();
    if (w == 0) {
        int nw = (blockDim.x + 31) >> 5;
        v = (lane < nw) ? sbuf[lane] : 0.f;
        #pragma unroll
        for (int o = 16; o; o >>= 1) v += __shfl_down_sync(0xffffffffu, v, o);
        if (lane == 0) sbuf[0] = v;
    }
    __syncthreads();
    return sbuf[0];
}

__device__ __forceinline__ float block_reduce_max(float v, float* sbuf) {
    __syncthreads();
    #pragma unroll
    for (int o = 16; o; o >>= 1) v = fmaxf(v, __shfl_down_sync(0xffffffffu, v, o));
    int lane = threadIdx.x & 31, w = threadIdx.x >> 5;
    if (lane == 0) sbuf[w] = v;
    __syncthreads();
    if (w == 0) {
        int nw = (blockDim.x + 31) >> 5;
        v = (lane < nw) ? sbuf[lane] : -3.4e38f;
        #pragma unroll
        for (int o = 16; o; o >>= 1) v = fmaxf(v, __shfl_down_sync(0xffffffffu, v, o));
        if (lane == 0) sbuf[0] = v;
    }
    __syncthreads();
    return sbuf[0];
}

// ---------------- embedding + LN + selection ----------------
__global__ void embed_kernel(const int* __restrict__ src, const int* __restrict__ seg,
                             const int* __restrict__ tib,
                             const float* __restrict__ we, const float* __restrict__ pe,
                             const float* __restrict__ se,
                             const float* __restrict__ g, const float* __restrict__ bta,
                             const float* __restrict__ sel, float* __restrict__ x)
{
    int t = blockIdx.x;
    int s = t % S_;
    __shared__ float e[H_];
    __shared__ float sbuf[32];
    int w = src[t], sg = seg[t];
    const float* wr = we + (size_t)w * H_;
    const float* pr = pe + (size_t)s * H_;
    const float* sr = se + (size_t)sg * H_;
    float lsum = 0.f, lsq = 0.f;
    for (int j = threadIdx.x; j < H_; j += blockDim.x) {
        float val = wr[j] + pr[j] + sr[j];
        e[j] = val; lsum += val; lsq += val * val;
    }
    float tot = block_reduce_sum(lsum, sbuf);
    float totsq = block_reduce_sum(lsq, sbuf);
    float mean = tot / H_;
    float var  = totsq / H_ - mean * mean;
    float inv  = rsqrtf(var + 1e-5f);
    float f = sel[tib[t]];
    float* xo = x + (size_t)t * H_;
    for (int j = threadIdx.x; j < H_; j += blockDim.x)
        xo[j] = ((e[j] - mean) * inv * g[j] + bta[j]) * f;
}

// ---------------- residual add + LN (in place on x) ----------------
__global__ void add_ln_kernel(float* __restrict__ x, const float* __restrict__ t,
                              const float* __restrict__ g, const float* __restrict__ bta)
{
    int row = blockIdx.x;
    __shared__ float e[H_];
    __shared__ float sbuf[32];
    float* xr = x + (size_t)row * H_;
    const float* tr = t + (size_t)row * H_;
    float lsum = 0.f, lsq = 0.f;
    for (int j = threadIdx.x; j < H_; j += blockDim.x) {
        float val = xr[j] + tr[j];
        e[j] = val; lsum += val; lsq += val * val;
    }
    float tot = block_reduce_sum(lsum, sbuf);
    float totsq = block_reduce_sum(lsq, sbuf);
    float mean = tot / H_;
    float var  = totsq / H_ - mean * mean;
    float inv  = rsqrtf(var + 1e-5f);
    for (int j = threadIdx.x; j < H_; j += blockDim.x)
        xr[j] = (e[j] - mean) * inv * g[j] + bta[j];
}

// ---------------- masked softmax over score rows ----------------
__global__ void softmax_kernel(float* __restrict__ sc, const int* __restrict__ seg)
{
    long row = blockIdx.x;
    int b = (int)(row / ((long)NH_ * S_));
    float* p = sc + row * S_;
    const int* segb = seg + (size_t)b * S_;
    __shared__ float sbuf[32];

    float vals[2];
    float lmax = -3.4e38f;
    #pragma unroll
    for (int r = 0; r < 2; r++) {
        int k = threadIdx.x + r * 256;
        float vv = p[k] + (segb[k] > 0 ? 0.f : -1e9f);
        vals[r] = vv;
        lmax = fmaxf(lmax, vv);
    }
    float mx = block_reduce_max(lmax, sbuf);
    float lsum = 0.f;
    #pragma unroll
    for (int r = 0; r < 2; r++) {
        vals[r] = __expf(vals[r] - mx);
        lsum += vals[r];
    }
    float sum = block_reduce_sum(lsum, sbuf);
    float rinv = 1.f / sum;
    #pragma unroll
    for (int r = 0; r < 2; r++) {
        int k = threadIdx.x + r * 256;
        p[k] = vals[r] * rinv;
    }
}

// =====================================================================
// TF32 tensor-core batched GEMM.
// Tile: BM=128, BN=64, BK=16. 256 threads = 8 warps (4 over M, 2 over N),
// each warp computes 32x32 via m16n8k8 tf32 mma (2 m-tiles x 4 n-tiles).
// REQUIRES: M%128==0, N%64==0, K%16==0 (all call sites satisfy this).
// TB=0: B row-major [K,N]; TB=1: B stored [N,K] (computes A @ B^T).
// ACT: 0 none, 1 gelu(tanh)
// =====================================================================
template<int TB, int ACT>
__global__ void __launch_bounds__(256)
mma_gemm(const float* __restrict__ A, const float* __restrict__ Bm,
         const float* __restrict__ bias, float* __restrict__ C,
         int K, int lda, int ldb, int ldc,
         long sAb, long sAh, long sBb, long sBh, long sCb, long sCh,
         int nh, float alpha)
{
    int bh = blockIdx.z;
    int b = bh / nh, h = bh - b * nh;
    A  += (long)b * sAb + (long)h * sAh;
    Bm += (long)b * sBb + (long)h * sBh;
    C  += (long)b * sCb + (long)h * sCh;

    // A: [m][k] with row stride 20 floats (conflict-free for frag pattern)
    // B: TB==0 -> [k][n] stride 72 ; TB==1 -> [n][k] stride 20
    __shared__ __align__(16) float As[2][128][20];
    __shared__ __align__(16) float Bs[2][1280];

    const int m0  = blockIdx.y * 128;
    const int n0  = blockIdx.x * 64;
    const int tid = threadIdx.x;
    const int lane = tid & 31, wid = tid >> 5;
    const int wm = wid & 3, wn = wid >> 2;
    const int g = lane >> 2, t = lane & 3;

    const int ntiles = K >> 4;

    auto copy_tile = [&](int kt, int buf) {
        int k0 = kt << 4;
        // A tile: 128 rows x 16 cols = 512 16B-chunks, 2 per thread
        {
            int c = tid;
            int row = c >> 2, kc = (c & 3) << 2;
            cp16(&As[buf][row][kc], A + (long)(m0 + row) * lda + k0 + kc);
            c += 256;
            row = c >> 2; kc = (c & 3) << 2;
            cp16(&As[buf][row][kc], A + (long)(m0 + row) * lda + k0 + kc);
        }
        if (TB == 0) {
            int kr = tid >> 4, nc = (tid & 15) << 2;
            cp16(&Bs[buf][kr * 72 + nc], Bm + (long)(k0 + kr) * ldb + n0 + nc);
        } else {
            int nr = tid >> 2, kc = (tid & 3) << 2;
            cp16(&Bs[buf][nr * 20 + kc], Bm + (long)(n0 + nr) * ldb + k0 + kc);
        }
        asm volatile("cp.async.commit_group;\n" ::);
    };

    float acc[2][4][4];
    #pragma unroll
    for (int i = 0; i < 2; i++)
        #pragma unroll
        for (int j = 0; j < 4; j++)
            #pragma unroll
            for (int r = 0; r < 4; r++) acc[i][j][r] = 0.f;

    copy_tile(0, 0);

    for (int kt = 0; kt < ntiles; kt++) {
        int buf = kt & 1;
        if (kt + 1 < ntiles) {
            copy_tile(kt + 1, buf ^ 1);
            asm volatile("cp.async.wait_group 1;\n" ::);
        } else {
            asm volatile("cp.async.wait_group 0;\n" ::);
        }
        __syncthreads();

        #pragma unroll
        for (int ks = 0; ks < 16; ks += 8) {
            uint32_t afr[2][4];
            #pragma unroll
            for (int mt = 0; mt < 2; mt++) {
                int r = wm * 32 + mt * 16;
                afr[mt][0] = f2tf32(As[buf][r + g    ][ks + t    ]);
                afr[mt][1] = f2tf32(As[buf][r + g + 8][ks + t    ]);
                afr[mt][2] = f2tf32(As[buf][r + g    ][ks + t + 4]);
                afr[mt][3] = f2tf32(As[buf][r + g + 8][ks + t + 4]);
            }
            uint32_t bfr[4][2];
            #pragma unroll
            for (int nt = 0; nt < 4; nt++) {
                int cth = wn * 32 + nt * 8 + g;
                if (TB == 0) {
                    bfr[nt][0] = f2tf32(Bs[buf][(ks + t    ) * 72 + cth]);
                    bfr[nt][1] = f2tf32(Bs[buf][(ks + t + 4) * 72 + cth]);
                } else {
                    bfr[nt][0] = f2tf32(Bs[buf][cth * 20 + ks + t    ]);
                    bfr[nt][1] = f2tf32(Bs[buf][cth * 20 + ks + t + 4]);
                }
            }
            #pragma unroll
            for (int mt = 0; mt < 2; mt++)
                #pragma unroll
                for (int nt = 0; nt < 4; nt++)
                    mma_tf32(acc[mt][nt], afr[mt], bfr[nt]);
        }
        __syncthreads();
    }

    // epilogue
    #pragma unroll
    for (int mt = 0; mt < 2; mt++) {
        #pragma unroll
        for (int nt = 0; nt < 4; nt++) {
            int row = m0 + wm * 32 + mt * 16 + g;
            int col = n0 + wn * 32 + nt * 8 + t * 2;
            float bv0 = 0.f, bv1 = 0.f;
            if (bias) { bv0 = bias[col]; bv1 = bias[col + 1]; }
            #pragma unroll
            for (int half = 0; half < 2; half++) {
                int r = row + half * 8;
                float v0 = acc[mt][nt][half * 2 + 0] * alpha + bv0;
                float v1 = acc[mt][nt][half * 2 + 1] * alpha + bv1;
                if (ACT == 1) { v0 = gelu_tanh(v0); v1 = gelu_tanh(v1); }
                *(float2*)&C[(long)r * ldc + col] = make_float2(v0, v1);
            }
        }
    }
}

// ---------------- small SIMT GEMM (pooler + classifier only) ----------------
#define BM 64
#define BN 64
#define BK 16
#define TM 4
#define TN 4

template<int ACT> // 0 none, 2 tanh
__global__ void gemm_kernel(const float* __restrict__ A, const float* __restrict__ Bm,
                            const float* __restrict__ bias, float* __restrict__ C,
                            int M, int N, int K, int lda, int ldb, int ldc)
{
    __shared__ float As[BK][BM + 1];
    __shared__ float Bs[BK][BN + 1];

    int m0 = blockIdx.y * BM;
    int n0 = blockIdx.x * BN;
    int tid = threadIdx.x;
    int tx = tid & 15, ty = tid >> 4;

    float acc[TM][TN] = {};

    for (int k0 = 0; k0 < K; k0 += BK) {
        #pragma unroll
        for (int i = tid; i < BM * BK; i += 256) {
            int m = i >> 4, k = i & 15;
            int gm = m0 + m, gk = k0 + k;
            As[k][m] = (gm < M && gk < K) ? A[(long)gm * lda + gk] : 0.f;
        }
        #pragma unroll
        for (int i = tid; i < BK * BN; i += 256) {
            int k = i >> 6, n = i & 63;
            int gk = k0 + k, gn = n0 + n;
            Bs[k][n] = (gk < K && gn < N) ? Bm[(long)gk * ldb + gn] : 0.f;
        }
        __syncthreads();
        #pragma unroll
        for (int k = 0; k < BK; k++) {
            float a[TM], bb[TN];
            #pragma unroll
            for (int i = 0; i < TM; i++) a[i] = As[k][ty * TM + i];
            #pragma unroll
            for (int j = 0; j < TN; j++) bb[j] = Bs[k][tx * TN + j];
            #pragma unroll
            for (int i = 0; i < TM; i++)
                #pragma unroll
                for (int j = 0; j < TN; j++)
                    acc[i][j] = fmaf(a[i], bb[j], acc[i][j]);
        }
        __syncthreads();
    }

    #pragma unroll
    for (int i = 0; i < TM; i++) {
        int gm = m0 + ty * TM + i;
        if (gm >= M) continue;
        #pragma unroll
        for (int j = 0; j < TN; j++) {
            int gn = n0 + tx * TN + j;
            if (gn >= N) continue;
            float v = acc[i][j];
            if (bias) v += bias[gn];
            if (ACT == 2) v = tanhf(v);
            C[(long)gm * ldc + gn] = v;
        }
    }
}

// ---------------- log-softmax + NLL loss + output write ----------------
__global__ void loss_kernel(const float* __restrict__ logits, const int* __restrict__ tgt,
                            float* __restrict__ out, int out_size)
{
    int lane = threadIdx.x;
    float lp = 0.f;
    if (lane < B_) {
        const float* row = logits + lane * LAB_;
        float mx = row[0];
        #pragma unroll
        for (int j = 1; j < LAB_; j++) mx = fmaxf(mx, row[j]);
        float s = 0.f;
        #pragma unroll
        for (int j = 0; j < LAB_; j++) s += expf(row[j] - mx);
        lp = row[tgt[lane]] - mx - logf(s);
    }
    #pragma unroll
    for (int o = 16; o; o >>= 1) lp += __shfl_down_sync(0xffffffffu, lp, o);
    int ofs = (out_size > B_ * LAB_) ? 1 : 0;
    if (lane == 0 && ofs) out[0] = -lp / (float)B_;
    for (int i = lane; i < B_ * LAB_; i += 32) out[ofs + i] = logits[i];
}

// ---------------- host launch ----------------
extern "C" void kernel_launch(void* const* d_in, const int* in_sizes, int n_in,
                              void* d_out, int out_size)
{
    const int*   src  = (const int*)d_in[0];
    const int*   seg  = (const int*)d_in[1];
    const int*   tgt  = (const int*)d_in[2];
    const int*   tib  = (const int*)d_in[3];
    const float* we   = (const float*)d_in[4];
    const float* pe   = (const float*)d_in[5];
    const float* se   = (const float*)d_in[6];
    const float* elng = (const float*)d_in[7];
    const float* elnb = (const float*)d_in[8];
    const float* Wq   = (const float*)d_in[9];
    const float* bq   = (const float*)d_in[10];
    const float* Wk   = (const float*)d_in[11];
    const float* bk   = (const float*)d_in[12];
    const float* Wv   = (const float*)d_in[13];
    const float* bv   = (const float*)d_in[14];
    const float* Wo   = (const float*)d_in[15];
    const float* bo   = (const float*)d_in[16];
    const float* ln1g = (const float*)d_in[17];
    const float* ln1b = (const float*)d_in[18];
    const float* Wf1  = (const float*)d_in[19];
    const float* bf1  = (const float*)d_in[20];
    const float* Wf2  = (const float*)d_in[21];
    const float* bf2  = (const float*)d_in[22];
    const float* ln2g = (const float*)d_in[23];
    const float* ln2b = (const float*)d_in[24];
    const float* Wp1  = (const float*)d_in[25];
    const float* bp1  = (const float*)d_in[26];
    const float* Wp2  = (const float*)d_in[27];
    const float* bp2  = (const float*)d_in[28];
    const float* sel  = (const float*)d_in[29];
    (void)in_sizes; (void)n_in;

    float *x, *q, *k, *v, *ctx, *tmp, *ff, *sc, *hidden, *logits;
    cudaGetSymbolAddress((void**)&x,     g_x);
    cudaGetSymbolAddress((void**)&q,     g_q);
    cudaGetSymbolAddress((void**)&k,     g_k);
    cudaGetSymbolAddress((void**)&v,     g_v);
    cudaGetSymbolAddress((void**)&ctx,   g_ctx);
    cudaGetSymbolAddress((void**)&tmp,   g_tmp);
    cudaGetSymbolAddress((void**)&ff,    g_ff);
    cudaGetSymbolAddress((void**)&sc,    g_sc);
    cudaGetSymbolAddress((void**)&hidden,g_hidden);
    cudaGetSymbolAddress((void**)&logits,g_logits);

    const int Mtok = B_ * S_;                    // 8192
    dim3 blk(256);
    dim3 gH (H_  / 64, Mtok / 128, 1);           // (12, 64)
    dim3 gFF(FF_ / 64, Mtok / 128, 1);           // (48, 64)

    embed_kernel<<<Mtok, 256>>>(src, seg, tib, we, pe, se, elng, elnb, sel, x);

    const long sQKVb = (long)S_ * H_;
    const long sHead = DH_;
    const long sScB  = (long)NH_ * S_ * S_;
    const long sScH  = (long)S_ * S_;

    for (int l = 0; l < L_; l++) {
        const float* wq  = Wq  + (size_t)l * H_ * H_;
        const float* wk  = Wk  + (size_t)l * H_ * H_;
        const float* wv  = Wv  + (size_t)l * H_ * H_;
        const float* wo  = Wo  + (size_t)l * H_ * H_;
        const float* wf1 = Wf1 + (size_t)l * H_ * FF_;
        const float* wf2 = Wf2 + (size_t)l * FF_ * H_;

        mma_gemm<0,0><<<gH, blk>>>(x, wq, bq + l * H_, q, H_, H_, H_, H_,
                                   0,0,0,0,0,0, 1, 1.f);
        mma_gemm<0,0><<<gH, blk>>>(x, wk, bk + l * H_, k, H_, H_, H_, H_,
                                   0,0,0,0,0,0, 1, 1.f);
        mma_gemm<0,0><<<gH, blk>>>(x, wv, bv + l * H_, v, H_, H_, H_, H_,
                                   0,0,0,0,0,0, 1, 1.f);

        // scores = q @ k^T / 8 per (b,h): M=S=512, N=S=512, K=DH=64
        dim3 gScore(S_ / 64, S_ / 128, B_ * NH_);
        mma_gemm<1,0><<<gScore, blk>>>(q, k, nullptr, sc, DH_, H_, H_, S_,
                                       sQKVb, sHead, sQKVb, sHead, sScB, sScH,
                                       NH_, 0.125f);

        softmax_kernel<<<B_ * NH_ * S_, 256>>>(sc, seg);

        // ctx = probs @ v per (b,h): M=512, N=64, K=512; writes (B,S,H) layout
        dim3 gCtx(1, S_ / 128, B_ * NH_);
        mma_gemm<0,0><<<gCtx, blk>>>(sc, v, nullptr, ctx, S_, S_, H_, H_,
                                     sScB, sScH, sQKVb, sHead, sQKVb, sHead,
                                     NH_, 1.f);

        mma_gemm<0,0><<<gH, blk>>>(ctx, wo, bo + l * H_, tmp, H_, H_, H_, H_,
                                   0,0,0,0,0,0, 1, 1.f);
        add_ln_kernel<<<Mtok, 256>>>(x, tmp, ln1g + l * H_, ln1b + l * H_);

        mma_gemm<0,1><<<gFF, blk>>>(x, wf1, bf1 + l * FF_, ff, H_, H_, FF_, FF_,
                                    0,0,0,0,0,0, 1, 1.f);
        mma_gemm<0,0><<<gH, blk>>>(ff, wf2, bf2 + l * H_, tmp, FF_, FF_, H_, H_,
                                   0,0,0,0,0,0, 1, 1.f);
        add_ln_kernel<<<Mtok, 256>>>(x, tmp, ln2g + l * H_, ln2b + l * H_);
    }

    // pooler (M=16): SIMT gemm; pooled rows are x[b*S, :] -> lda = S*H
    dim3 gPool((H_ + BN - 1) / BN, 1, 1);
    gemm_kernel<2><<<gPool, blk>>>(x, Wp1, bp1, hidden, B_, H_, H_,
                                   S_ * H_, H_, H_);
    dim3 gCls(1, 1, 1);
    gemm_kernel<0><<<gCls, blk>>>(hidden, Wp2, bp2, logits, B_, LAB_, H_,
                                  H_, LAB_, LAB_);

    loss_kernel<<<1, 32>>>(logits, tgt, (float*)d_out, out_size);
}

// round 3
// speedup vs baseline: 6.1077x; 1.0916x over previous
#include <cuda_runtime.h>
#include <cuda_bf16.h>
#include <math.h>
#include <stdint.h>

#define B_   16
#define S_   512
#define H_   768
#define NH_  12
#define L_   6
#define FF_  3072
#define DH_  64
#define LAB_ 10

// ---------------- scratch (device globals; no allocations allowed) ----------
__device__ float g_x  [(size_t)B_*S_*H_];
__device__ float g_q  [(size_t)B_*S_*H_];
__device__ float g_k  [(size_t)B_*S_*H_];
__device__ float g_v  [(size_t)B_*S_*H_];
__device__ float g_ctx[(size_t)B_*S_*H_];
__device__ float g_tmp[(size_t)B_*S_*H_];
__device__ float g_ff [(size_t)B_*S_*FF_];
__device__ float g_sc [(size_t)B_*NH_*S_*S_];
__device__ float g_hidden[(size_t)B_*H_];
__device__ float g_logits[(size_t)B_*LAB_];
// transposed + tf32-rounded weights
__device__ float g_wqT [(size_t)L_*H_*H_];
__device__ float g_wkT [(size_t)L_*H_*H_];
__device__ float g_wvT [(size_t)L_*H_*H_];
__device__ float g_woT [(size_t)L_*H_*H_];
__device__ float g_wf1T[(size_t)L_*FF_*H_];
__device__ float g_wf2T[(size_t)L_*H_*FF_];

// ---------------- small helpers ----------------
__device__ __forceinline__ uint32_t f2tf32(float f) {
    uint32_t u;
    asm("cvt.rna.tf32.f32 %0, %1;" : "=r"(u) : "f"(f));
    return u;
}

__device__ __forceinline__ void cp16(void* s, const void* g) {
    uint32_t sa = (uint32_t)__cvta_generic_to_shared(s);
    asm volatile("cp.async.ca.shared.global [%0], [%1], 16;\n" :: "r"(sa), "l"(g));
}

__device__ __forceinline__ void ldsm4(uint32_t* r, const void* p) {
    uint32_t a = (uint32_t)__cvta_generic_to_shared(p);
    asm volatile("ldmatrix.sync.aligned.m8n8.x4.shared.b16 {%0,%1,%2,%3}, [%4];"
                 : "=r"(r[0]), "=r"(r[1]), "=r"(r[2]), "=r"(r[3]) : "r"(a));
}

__device__ __forceinline__ void mma_tf32(float* c, const uint32_t* a, const uint32_t* b) {
    asm volatile(
        "mma.sync.aligned.m16n8k8.row.col.f32.tf32.tf32.f32 "
        "{%0,%1,%2,%3}, {%4,%5,%6,%7}, {%8,%9}, {%0,%1,%2,%3};\n"
        : "+f"(c[0]), "+f"(c[1]), "+f"(c[2]), "+f"(c[3])
        : "r"(a[0]), "r"(a[1]), "r"(a[2]), "r"(a[3]), "r"(b[0]), "r"(b[1]));
}

__device__ __forceinline__ float gelu_tanh(float v) {
    float c = v * v * v;
    return 0.5f * v * (1.f + tanhf(0.7978845608028654f * (v + 0.044715f * c)));
}

// ---------------- block reductions ----------------
__device__ __forceinline__ float block_reduce_sum(float v, float* sbuf) {
    __syncthreads();
    #pragma unroll
    for (int o = 16; o; o >>= 1) v += __shfl_down_sync(0xffffffffu, v, o);
    int lane = threadIdx.x & 31, w = threadIdx.x >> 5;
    if (lane == 0) sbuf[w] = v;
    __syncthreads();
    if (w == 0) {
        int nw = (blockDim.x + 31) >> 5;
        v = (lane < nw) ? sbuf[lane] : 0.f;
        #pragma unroll
        for (int o = 16; o; o >>= 1) v += __shfl_down_sync(0xffffffffu, v, o);
        if (lane == 0) sbuf[0] = v;
    }
    __syncthreads();
    return sbuf[0];
}

__device__ __forceinline__ float block_reduce_max(float v, float* sbuf) {
    __syncthreads();
    #pragma unroll
    for (int o = 16; o; o >>= 1) v = fmaxf(v, __shfl_down_sync(0xffffffffu, v, o));
    int lane = threadIdx.x & 31, w = threadIdx.x >> 5;
    if (lane == 0) sbuf[w] = v;
    __syncthreads();
    if (w == 0) {
        int nw = (blockDim.x + 31) >> 5;
        v = (lane < nw) ? sbuf[lane] : -3.4e38f;
        #pragma unroll
        for (int o = 16; o; o >>= 1) v = fmaxf(v, __shfl_down_sync(0xffffffffu, v, o));
        if (lane == 0) sbuf[0] = v;
    }
    __syncthreads();
    return sbuf[0];
}

// ---------------- weight transpose + tf32 round (once per launch) ----------
__global__ void transpose_cvt(const float* __restrict__ in, float* __restrict__ out,
                              int R, int C)
{
    in  += (size_t)blockIdx.z * R * C;
    out += (size_t)blockIdx.z * R * C;
    __shared__ float t[32][33];
    int c0 = blockIdx.x * 32, r0 = blockIdx.y * 32;
    int tx = threadIdx.x, ty = threadIdx.y;
    #pragma unroll
    for (int i = 0; i < 32; i += 8)
        t[ty + i][tx] = in[(size_t)(r0 + ty + i) * C + c0 + tx];
    __syncthreads();
    #pragma unroll
    for (int i = 0; i < 32; i += 8)
        out[(size_t)(c0 + ty + i) * R + r0 + tx] = __uint_as_float(f2tf32(t[tx][ty + i]));
}

// ---------------- embedding + LN + selection ----------------
__global__ void embed_kernel(const int* __restrict__ src, const int* __restrict__ seg,
                             const int* __restrict__ tib,
                             const float* __restrict__ we, const float* __restrict__ pe,
                             const float* __restrict__ se,
                             const float* __restrict__ g, const float* __restrict__ bta,
                             const float* __restrict__ sel, float* __restrict__ x)
{
    int t = blockIdx.x;
    int s = t % S_;
    __shared__ float e[H_];
    __shared__ float sbuf[32];
    int w = src[t], sg = seg[t];
    const float* wr = we + (size_t)w * H_;
    const float* pr = pe + (size_t)s * H_;
    const float* sr = se + (size_t)sg * H_;
    float lsum = 0.f, lsq = 0.f;
    for (int j = threadIdx.x; j < H_; j += blockDim.x) {
        float val = wr[j] + pr[j] + sr[j];
        e[j] = val; lsum += val; lsq += val * val;
    }
    float tot = block_reduce_sum(lsum, sbuf);
    float totsq = block_reduce_sum(lsq, sbuf);
    float mean = tot / H_;
    float var  = totsq / H_ - mean * mean;
    float inv  = rsqrtf(var + 1e-5f);
    float f = sel[tib[t]];
    float* xo = x + (size_t)t * H_;
    for (int j = threadIdx.x; j < H_; j += blockDim.x)
        xo[j] = ((e[j] - mean) * inv * g[j] + bta[j]) * f;
}

// ---------------- residual add + LN (in place on x) ----------------
__global__ void add_ln_kernel(float* __restrict__ x, const float* __restrict__ t,
                              const float* __restrict__ g, const float* __restrict__ bta)
{
    int row = blockIdx.x;
    __shared__ float e[H_];
    __shared__ float sbuf[32];
    float* xr = x + (size_t)row * H_;
    const float* tr = t + (size_t)row * H_;
    float lsum = 0.f, lsq = 0.f;
    for (int j = threadIdx.x; j < H_; j += blockDim.x) {
        float val = xr[j] + tr[j];
        e[j] = val; lsum += val; lsq += val * val;
    }
    float tot = block_reduce_sum(lsum, sbuf);
    float totsq = block_reduce_sum(lsq, sbuf);
    float mean = tot / H_;
    float var  = totsq / H_ - mean * mean;
    float inv  = rsqrtf(var + 1e-5f);
    for (int j = threadIdx.x; j < H_; j += blockDim.x)
        xr[j] = (e[j] - mean) * inv * g[j] + bta[j];
}

// ---------------- masked softmax; writes tf32-rounded probs ----------------
__global__ void softmax_kernel(float* __restrict__ sc, const int* __restrict__ seg)
{
    long row = blockIdx.x;
    int b = (int)(row / ((long)NH_ * S_));
    float* p = sc + row * S_;
    const int* segb = seg + (size_t)b * S_;
    __shared__ float sbuf[32];

    float vals[2];
    float lmax = -3.4e38f;
    #pragma unroll
    for (int r = 0; r < 2; r++) {
        int k = threadIdx.x + r * 256;
        float vv = p[k] + (segb[k] > 0 ? 0.f : -1e9f);
        vals[r] = vv;
        lmax = fmaxf(lmax, vv);
    }
    float mx = block_reduce_max(lmax, sbuf);
    float lsum = 0.f;
    #pragma unroll
    for (int r = 0; r < 2; r++) {
        vals[r] = __expf(vals[r] - mx);
        lsum += vals[r];
    }
    float sum = block_reduce_sum(lsum, sbuf);
    float rinv = 1.f / sum;
    #pragma unroll
    for (int r = 0; r < 2; r++) {
        int k = threadIdx.x + r * 256;
        p[k] = __uint_as_float(f2tf32(vals[r] * rinv));
    }
}

// =====================================================================
// TF32 tensor-core batched GEMM, ldmatrix fragment feed.
// BM=128, BN=64, BK=16, 256 threads = 8 warps (wm 0..3, wn 0..1),
// warp tile 32x32 (mt=2, nt=4), m16n8k8 tf32 mma, 3-stage cp.async.
// LDMB=1: B in smem [n][k] (stride 20), fed by ldmatrix (needs B gmem [N][K]).
// LDMB=0: B in smem [k][n] (stride 72), scalar loads (B gmem [K][N]).
// CVT_A=1: A is raw fp32 -> cvt fragments; 0: A already tf32-rounded.
// ACT: 0 none, 1 gelu ; OTF: 1 -> round outputs to tf32 bits.
// =====================================================================
template<int LDMB, int CVT_A, int ACT, int OTF>
__global__ void __launch_bounds__(256)
mma_gemm(const float* __restrict__ A, const float* __restrict__ Bm,
         const float* __restrict__ bias, float* __restrict__ C,
         int K, int lda, int ldb, int ldc,
         long sAb, long sAh, long sBb, long sBh, long sCb, long sCh,
         int nh, float alpha)
{
    int bh = blockIdx.z;
    int b = bh / nh, h = bh - b * nh;
    A  += (long)b * sAb + (long)h * sAh;
    Bm += (long)b * sBb + (long)h * sBh;
    C  += (long)b * sCb + (long)h * sCh;

    constexpr int BSZ = LDMB ? (64 * 20) : (16 * 72);
    __shared__ __align__(16) float As[3][128 * 20];
    __shared__ __align__(16) float Bs[3][BSZ];

    const int m0  = blockIdx.y * 128;
    const int n0  = blockIdx.x * 64;
    const int tid = threadIdx.x;
    const int lane = tid & 31, wid = tid >> 5;
    const int wm = wid & 3, wn = wid >> 2;
    const int g = lane >> 2, t = lane & 3;

    // ldmatrix lane addressing (m8n8.x4 -> 4 8x4-tf32 matrices)
    const int a_row = wm * 32 + (lane & 7) + ((lane >> 3) & 1) * 8;  // + mt*16
    const int a_col = (lane >> 4) * 4;                               // + ks
    const int b_row = wn * 32 + (lane >> 4) * 8 + (lane & 7);        // + p*16
    const int b_col = ((lane >> 3) & 1) * 4;                         // + ks

    const int ntiles = K >> 4;

    auto copy_tile = [&](int kt, int buf) {
        int k0 = kt << 4;
        {
            int c = tid;
            int row = c >> 2, kc = (c & 3) << 2;
            cp16(&As[buf][row * 20 + kc], A + (long)(m0 + row) * lda + k0 + kc);
            c += 256;
            row = c >> 2; kc = (c & 3) << 2;
            cp16(&As[buf][row * 20 + kc], A + (long)(m0 + row) * lda + k0 + kc);
        }
        if (LDMB) {
            int nr = tid >> 2, kc = (tid & 3) << 2;
            cp16(&Bs[buf][nr * 20 + kc], Bm + (long)(n0 + nr) * ldb + k0 + kc);
        } else {
            int kr = tid >> 4, nc = (tid & 15) << 2;
            cp16(&Bs[buf][kr * 72 + nc], Bm + (long)(k0 + kr) * ldb + n0 + nc);
        }
        asm volatile("cp.async.commit_group;\n" ::);
    };

    float acc[2][4][4];
    #pragma unroll
    for (int i = 0; i < 2; i++)
        #pragma unroll
        for (int j = 0; j < 4; j++)
            #pragma unroll
            for (int r = 0; r < 4; r++) acc[i][j][r] = 0.f;

    copy_tile(0, 0);
    if (ntiles > 1) copy_tile(1, 1);

    for (int kt = 0; kt < ntiles; kt++) {
        int buf = kt % 3;
        if (kt + 2 < ntiles) {
            asm volatile("cp.async.wait_group 1;\n" ::);
        } else {
            asm volatile("cp.async.wait_group 0;\n" ::);
        }
        __syncthreads();
        if (kt + 2 < ntiles) copy_tile(kt + 2, (kt + 2) % 3);

        #pragma unroll
        for (int ks = 0; ks < 16; ks += 8) {
            uint32_t afr[2][4];
            #pragma unroll
            for (int mt = 0; mt < 2; mt++) {
                ldsm4(afr[mt], &As[buf][(a_row + mt * 16) * 20 + a_col + ks]);
                if (CVT_A) {
                    #pragma unroll
                    for (int r = 0; r < 4; r++)
                        afr[mt][r] = f2tf32(__uint_as_float(afr[mt][r]));
                }
            }
            uint32_t bfr[4][2];
            if (LDMB) {
                #pragma unroll
                for (int p = 0; p < 2; p++) {
                    uint32_t rr[4];
                    ldsm4(rr, &Bs[buf][(b_row + p * 16) * 20 + b_col + ks]);
                    bfr[2 * p][0] = rr[0]; bfr[2 * p][1] = rr[1];
                    bfr[2 * p + 1][0] = rr[2]; bfr[2 * p + 1][1] = rr[3];
                }
            } else {
                #pragma unroll
                for (int nt = 0; nt < 4; nt++) {
                    int cth = wn * 32 + nt * 8 + g;
                    bfr[nt][0] = __float_as_uint(Bs[buf][(ks + t) * 72 + cth]);
                    bfr[nt][1] = __float_as_uint(Bs[buf][(ks + t + 4) * 72 + cth]);
                }
            }
            #pragma unroll
            for (int mt = 0; mt < 2; mt++)
                #pragma unroll
                for (int nt = 0; nt < 4; nt++)
                    mma_tf32(acc[mt][nt], afr[mt], bfr[nt]);
        }
        __syncthreads();
    }

    // epilogue
    #pragma unroll
    for (int mt = 0; mt < 2; mt++) {
        #pragma unroll
        for (int nt = 0; nt < 4; nt++) {
            int row = m0 + wm * 32 + mt * 16 + g;
            int col = n0 + wn * 32 + nt * 8 + t * 2;
            float bv0 = 0.f, bv1 = 0.f;
            if (bias) { bv0 = bias[col]; bv1 = bias[col + 1]; }
            #pragma unroll
            for (int half = 0; half < 2; half++) {
                int r = row + half * 8;
                float v0 = acc[mt][nt][half * 2 + 0] * alpha + bv0;
                float v1 = acc[mt][nt][half * 2 + 1] * alpha + bv1;
                if (ACT == 1) { v0 = gelu_tanh(v0); v1 = gelu_tanh(v1); }
                if (OTF) {
                    v0 = __uint_as_float(f2tf32(v0));
                    v1 = __uint_as_float(f2tf32(v1));
                }
                *(float2*)&C[(long)r * ldc + col] = make_float2(v0, v1);
            }
        }
    }
}

// ---------------- small SIMT GEMM (pooler + classifier only) ----------------
#define BM 64
#define BN 64
#define BK 16
#define TM 4
#define TN 4

template<int ACT> // 0 none, 2 tanh
__global__ void gemm_kernel(const float* __restrict__ A, const float* __restrict__ Bm,
                            const float* __restrict__ bias, float* __restrict__ C,
                            int M, int N, int K, int lda, int ldb, int ldc)
{
    __shared__ float As[BK][BM + 1];
    __shared__ float Bs[BK][BN + 1];

    int m0 = blockIdx.y * BM;
    int n0 = blockIdx.x * BN;
    int tid = threadIdx.x;
    int tx = tid & 15, ty = tid >> 4;

    float acc[TM][TN] = {};

    for (int k0 = 0; k0 < K; k0 += BK) {
        #pragma unroll
        for (int i = tid; i < BM * BK; i += 256) {
            int m = i >> 4, k = i & 15;
            int gm = m0 + m, gk = k0 + k;
            As[k][m] = (gm < M && gk < K) ? A[(long)gm * lda + gk] : 0.f;
        }
        #pragma unroll
        for (int i = tid; i < BK * BN; i += 256) {
            int k = i >> 6, n = i & 63;
            int gk = k0 + k, gn = n0 + n;
            Bs[k][n] = (gk < K && gn < N) ? Bm[(long)gk * ldb + gn] : 0.f;
        }
        __syncthreads();
        #pragma unroll
        for (int k = 0; k < BK; k++) {
            float a[TM], bb[TN];
            #pragma unroll
            for (int i = 0; i < TM; i++) a[i] = As[k][ty * TM + i];
            #pragma unroll
            for (int j = 0; j < TN; j++) bb[j] = Bs[k][tx * TN + j];
            #pragma unroll
            for (int i = 0; i < TM; i++)
                #pragma unroll
                for (int j = 0; j < TN; j++)
                    acc[i][j] = fmaf(a[i], bb[j], acc[i][j]);
        }
        __syncthreads();
    }

    #pragma unroll
    for (int i = 0; i < TM; i++) {
        int gm = m0 + ty * TM + i;
        if (gm >= M) continue;
        #pragma unroll
        for (int j = 0; j < TN; j++) {
            int gn = n0 + tx * TN + j;
            if (gn >= N) continue;
            float v = acc[i][j];
            if (bias) v += bias[gn];
            if (ACT == 2) v = tanhf(v);
            C[(long)gm * ldc + gn] = v;
        }
    }
}

// ---------------- log-softmax + NLL loss + output write ----------------
__global__ void loss_kernel(const float* __restrict__ logits, const int* __restrict__ tgt,
                            float* __restrict__ out, int out_size)
{
    int lane = threadIdx.x;
    float lp = 0.f;
    if (lane < B_) {
        const float* row = logits + lane * LAB_;
        float mx = row[0];
        #pragma unroll
        for (int j = 1; j < LAB_; j++) mx = fmaxf(mx, row[j]);
        float s = 0.f;
        #pragma unroll
        for (int j = 0; j < LAB_; j++) s += expf(row[j] - mx);
        lp = row[tgt[lane]] - mx - logf(s);
    }
    #pragma unroll
    for (int o = 16; o; o >>= 1) lp += __shfl_down_sync(0xffffffffu, lp, o);
    int ofs = (out_size > B_ * LAB_) ? 1 : 0;
    if (lane == 0 && ofs) out[0] = -lp / (float)B_;
    for (int i = lane; i < B_ * LAB_; i += 32) out[ofs + i] = logits[i];
}

// ---------------- host launch ----------------
extern "C" void kernel_launch(void* const* d_in, const int* in_sizes, int n_in,
                              void* d_out, int out_size)
{
    const int*   src  = (const int*)d_in[0];
    const int*   seg  = (const int*)d_in[1];
    const int*   tgt  = (const int*)d_in[2];
    const int*   tib  = (const int*)d_in[3];
    const float* we   = (const float*)d_in[4];
    const float* pe   = (const float*)d_in[5];
    const float* se   = (const float*)d_in[6];
    const float* elng = (const float*)d_in[7];
    const float* elnb = (const float*)d_in[8];
    const float* Wq   = (const float*)d_in[9];
    const float* bq   = (const float*)d_in[10];
    const float* Wk   = (const float*)d_in[11];
    const float* bk   = (const float*)d_in[12];
    const float* Wv   = (const float*)d_in[13];
    const float* bv   = (const float*)d_in[14];
    const float* Wo   = (const float*)d_in[15];
    const float* bo   = (const float*)d_in[16];
    const float* ln1g = (const float*)d_in[17];
    const float* ln1b = (const float*)d_in[18];
    const float* Wf1  = (const float*)d_in[19];
    const float* bf1  = (const float*)d_in[20];
    const float* Wf2  = (const float*)d_in[21];
    const float* bf2  = (const float*)d_in[22];
    const float* ln2g = (const float*)d_in[23];
    const float* ln2b = (const float*)d_in[24];
    const float* Wp1  = (const float*)d_in[25];
    const float* bp1  = (const float*)d_in[26];
    const float* Wp2  = (const float*)d_in[27];
    const float* bp2  = (const float*)d_in[28];
    const float* sel  = (const float*)d_in[29];
    (void)in_sizes; (void)n_in;

    float *x, *q, *k, *v, *ctx, *tmp, *ff, *sc, *hidden, *logits;
    float *wqT, *wkT, *wvT, *woT, *wf1T, *wf2T;
    cudaGetSymbolAddress((void**)&x,     g_x);
    cudaGetSymbolAddress((void**)&q,     g_q);
    cudaGetSymbolAddress((void**)&k,     g_k);
    cudaGetSymbolAddress((void**)&v,     g_v);
    cudaGetSymbolAddress((void**)&ctx,   g_ctx);
    cudaGetSymbolAddress((void**)&tmp,   g_tmp);
    cudaGetSymbolAddress((void**)&ff,    g_ff);
    cudaGetSymbolAddress((void**)&sc,    g_sc);
    cudaGetSymbolAddress((void**)&hidden,g_hidden);
    cudaGetSymbolAddress((void**)&logits,g_logits);
    cudaGetSymbolAddress((void**)&wqT,   g_wqT);
    cudaGetSymbolAddress((void**)&wkT,   g_wkT);
    cudaGetSymbolAddress((void**)&wvT,   g_wvT);
    cudaGetSymbolAddress((void**)&woT,   g_woT);
    cudaGetSymbolAddress((void**)&wf1T,  g_wf1T);
    cudaGetSymbolAddress((void**)&wf2T,  g_wf2T);

    const int Mtok = B_ * S_;                    // 8192
    dim3 blk(256);
    dim3 gH (H_  / 64, Mtok / 128, 1);
    dim3 gFF(FF_ / 64, Mtok / 128, 1);

    // weight transposes + tf32 rounding
    {
        dim3 tb(32, 8);
        dim3 gHH(H_ / 32, H_ / 32, L_);
        transpose_cvt<<<gHH, tb>>>(Wq, wqT, H_, H_);
        transpose_cvt<<<gHH, tb>>>(Wk, wkT, H_, H_);
        transpose_cvt<<<gHH, tb>>>(Wv, wvT, H_, H_);
        transpose_cvt<<<gHH, tb>>>(Wo, woT, H_, H_);
        dim3 gF1(FF_ / 32, H_ / 32, L_);   // Wf1 [H,FF] -> [FF,H]
        transpose_cvt<<<gF1, tb>>>(Wf1, wf1T, H_, FF_);
        dim3 gF2(H_ / 32, FF_ / 32, L_);   // Wf2 [FF,H] -> [H,FF]
        transpose_cvt<<<gF2, tb>>>(Wf2, wf2T, FF_, H_);
    }

    embed_kernel<<<Mtok, 256>>>(src, seg, tib, we, pe, se, elng, elnb, sel, x);

    const long sQKVb = (long)S_ * H_;
    const long sHead = DH_;
    const long sScB  = (long)NH_ * S_ * S_;
    const long sScH  = (long)S_ * S_;

    for (int l = 0; l < L_; l++) {
        const float* wq  = wqT  + (size_t)l * H_ * H_;
        const float* wk  = wkT  + (size_t)l * H_ * H_;
        const float* wv  = wvT  + (size_t)l * H_ * H_;
        const float* wo  = woT  + (size_t)l * H_ * H_;
        const float* wf1 = wf1T + (size_t)l * H_ * FF_;
        const float* wf2 = wf2T + (size_t)l * FF_ * H_;

        // QKV: A = x (fp32 -> cvt), B = W^T [N][K], outputs tf32-rounded
        mma_gemm<1,1,0,1><<<gH, blk>>>(x, wq, bq + l * H_, q, H_, H_, H_, H_,
                                       0,0,0,0,0,0, 1, 1.f);
        mma_gemm<1,1,0,1><<<gH, blk>>>(x, wk, bk + l * H_, k, H_, H_, H_, H_,
                                       0,0,0,0,0,0, 1, 1.f);
        mma_gemm<1,1,0,1><<<gH, blk>>>(x, wv, bv + l * H_, v, H_, H_, H_, H_,
                                       0,0,0,0,0,0, 1, 1.f);

        // scores = q @ k^T / 8 per (b,h): k is [token][dh] = [n][k] layout
        dim3 gScore(S_ / 64, S_ / 128, B_ * NH_);
        mma_gemm<1,0,0,0><<<gScore, blk>>>(q, k, nullptr, sc, DH_, H_, H_, S_,
                                           sQKVb, sHead, sQKVb, sHead, sScB, sScH,
                                           NH_, 0.125f);

        softmax_kernel<<<B_ * NH_ * S_, 256>>>(sc, seg);

        // ctx = probs @ v per (b,h): B = v [key][dh] = [k][n] -> scalar path
        dim3 gCtx(1, S_ / 128, B_ * NH_);
        mma_gemm<0,0,0,1><<<gCtx, blk>>>(sc, v, nullptr, ctx, S_, S_, H_, H_,
                                         sScB, sScH, sQKVb, sHead, sQKVb, sHead,
                                         NH_, 1.f);

        // Wo: A = ctx (tf32), B = Wo^T
        mma_gemm<1,0,0,0><<<gH, blk>>>(ctx, wo, bo + l * H_, tmp, H_, H_, H_, H_,
                                       0,0,0,0,0,0, 1, 1.f);
        add_ln_kernel<<<Mtok, 256>>>(x, tmp, ln1g + l * H_, ln1b + l * H_);

        // FFN1: A = x (fp32), B = Wf1^T, gelu, output tf32
        mma_gemm<1,1,1,1><<<gFF, blk>>>(x, wf1, bf1 + l * FF_, ff, H_, H_, H_, FF_,
                                        0,0,0,0,0,0, 1, 1.f);
        // FFN2: A = ff (tf32), B = Wf2^T
        mma_gemm<1,0,0,0><<<gH, blk>>>(ff, wf2, bf2 + l * H_, tmp, FF_, FF_, FF_, H_,
                                       0,0,0,0,0,0, 1, 1.f);
        add_ln_kernel<<<Mtok, 256>>>(x, tmp, ln2g + l * H_, ln2b + l * H_);
    }

    dim3 gPool((H_ + BN - 1) / BN, 1, 1);
    gemm_kernel<2><<<gPool, blk>>>(x, Wp1, bp1, hidden, B_, H_, H_,
                                   S_ * H_, H_, H_);
    dim3 gCls(1, 1, 1);
    gemm_kernel<0><<<gCls, blk>>>(hidden, Wp2, bp2, logits, B_, LAB_, H_,
                                  H_, LAB_, LAB_);

    loss_kernel<<<1, 32>>>(logits, tgt, (float*)d_out, out_size);
}

// round 4
// speedup vs baseline: 7.5024x; 1.2283x over previous
#include <cuda_runtime.h>
#include <cuda_bf16.h>
#include <math.h>
#include <stdint.h>

#define B_   16
#define S_   512
#define H_   768
#define NH_  12
#define L_   6
#define FF_  3072
#define DH_  64
#define LAB_ 10
#define QKVN 2304          // 3*H

// ---------------- scratch (device globals; no allocations allowed) ----------
__device__ float g_x  [(size_t)B_*S_*H_];
__device__ float g_qkv[(size_t)B_*S_*QKVN];
__device__ float g_ctx[(size_t)B_*S_*H_];
__device__ float g_tmp[(size_t)B_*S_*H_];
__device__ float g_ff [(size_t)B_*S_*FF_];
__device__ float g_hidden[(size_t)B_*H_];
__device__ float g_logits[(size_t)B_*LAB_];
// transposed + tf32-rounded weights
__device__ float g_wqkvT[(size_t)L_*QKVN*H_];
__device__ float g_woT  [(size_t)L_*H_*H_];
__device__ float g_wf1T [(size_t)L_*FF_*H_];
__device__ float g_wf2T [(size_t)L_*H_*FF_];
__device__ float g_bqkv [(size_t)L_*QKVN];

// ---------------- small helpers ----------------
__device__ __forceinline__ uint32_t f2tf32(float f) {
    uint32_t u;
    asm("cvt.rna.tf32.f32 %0, %1;" : "=r"(u) : "f"(f));
    return u;
}

__device__ __forceinline__ void cp16(void* s, const void* g) {
    uint32_t sa = (uint32_t)__cvta_generic_to_shared(s);
    asm volatile("cp.async.ca.shared.global [%0], [%1], 16;\n" :: "r"(sa), "l"(g));
}

__device__ __forceinline__ void ldsm4(uint32_t* r, const void* p) {
    uint32_t a = (uint32_t)__cvta_generic_to_shared(p);
    asm volatile("ldmatrix.sync.aligned.m8n8.x4.shared.b16 {%0,%1,%2,%3}, [%4];"
                 : "=r"(r[0]), "=r"(r[1]), "=r"(r[2]), "=r"(r[3]) : "r"(a));
}

__device__ __forceinline__ void mma_tf32(float* c, const uint32_t* a, const uint32_t* b) {
    asm volatile(
        "mma.sync.aligned.m16n8k8.row.col.f32.tf32.tf32.f32 "
        "{%0,%1,%2,%3}, {%4,%5,%6,%7}, {%8,%9}, {%0,%1,%2,%3};\n"
        : "+f"(c[0]), "+f"(c[1]), "+f"(c[2]), "+f"(c[3])
        : "r"(a[0]), "r"(a[1]), "r"(a[2]), "r"(a[3]), "r"(b[0]), "r"(b[1]));
}

__device__ __forceinline__ float gelu_tanh(float v) {
    float c = v * v * v;
    return 0.5f * v * (1.f + tanhf(0.7978845608028654f * (v + 0.044715f * c)));
}

// ---------------- block reductions ----------------
__device__ __forceinline__ float block_reduce_sum(float v, float* sbuf) {
    __syncthreads();
    #pragma unroll
    for (int o = 16; o; o >>= 1) v += __shfl_down_sync(0xffffffffu, v, o);
    int lane = threadIdx.x & 31, w = threadIdx.x >> 5;
    if (lane == 0) sbuf[w] = v;
    __syncthreads();
    if (w == 0) {
        int nw = (blockDim.x + 31) >> 5;
        v = (lane < nw) ? sbuf[lane] : 0.f;
        #pragma unroll
        for (int o = 16; o; o >>= 1) v += __shfl_down_sync(0xffffffffu, v, o);
        if (lane == 0) sbuf[0] = v;
    }
    __syncthreads();
    return sbuf[0];
}

// ---------------- weight transpose + tf32 round (once per launch) ----------
__global__ void transpose_cvt(const float* __restrict__ in, float* __restrict__ out,
                              int R, int C, long ozs)
{
    in  += (size_t)blockIdx.z * R * C;
    out += (size_t)blockIdx.z * ozs;
    __shared__ float t[32][33];
    int c0 = blockIdx.x * 32, r0 = blockIdx.y * 32;
    int tx = threadIdx.x, ty = threadIdx.y;
    #pragma unroll
    for (int i = 0; i < 32; i += 8)
        t[ty + i][tx] = in[(size_t)(r0 + ty + i) * C + c0 + tx];
    __syncthreads();
    #pragma unroll
    for (int i = 0; i < 32; i += 8)
        out[(size_t)(c0 + ty + i) * R + r0 + tx] = __uint_as_float(f2tf32(t[tx][ty + i]));
}

__global__ void concat_bias(const float* __restrict__ bq, const float* __restrict__ bk,
                            const float* __restrict__ bv, float* __restrict__ out)
{
    int i = blockIdx.x * 256 + threadIdx.x;
    if (i >= L_ * QKVN) return;
    int l = i / QKVN, r = i - l * QKVN;
    float val;
    if (r < H_)            val = bq[l * H_ + r];
    else if (r < 2 * H_)   val = bk[l * H_ + r - H_];
    else                   val = bv[l * H_ + r - 2 * H_];
    out[i] = val;
}

// ---------------- embedding + LN + selection ----------------
__global__ void embed_kernel(const int* __restrict__ src, const int* __restrict__ seg,
                             const int* __restrict__ tib,
                             const float* __restrict__ we, const float* __restrict__ pe,
                             const float* __restrict__ se,
                             const float* __restrict__ g, const float* __restrict__ bta,
                             const float* __restrict__ sel, float* __restrict__ x)
{
    int t = blockIdx.x;
    int s = t % S_;
    __shared__ float e[H_];
    __shared__ float sbuf[32];
    int w = src[t], sg = seg[t];
    const float* wr = we + (size_t)w * H_;
    const float* pr = pe + (size_t)s * H_;
    const float* sr = se + (size_t)sg * H_;
    float lsum = 0.f, lsq = 0.f;
    for (int j = threadIdx.x; j < H_; j += blockDim.x) {
        float val = wr[j] + pr[j] + sr[j];
        e[j] = val; lsum += val; lsq += val * val;
    }
    float tot = block_reduce_sum(lsum, sbuf);
    float totsq = block_reduce_sum(lsq, sbuf);
    float mean = tot / H_;
    float var  = totsq / H_ - mean * mean;
    float inv  = rsqrtf(var + 1e-5f);
    float f = sel[tib[t]];
    float* xo = x + (size_t)t * H_;
    for (int j = threadIdx.x; j < H_; j += blockDim.x)
        xo[j] = ((e[j] - mean) * inv * g[j] + bta[j]) * f;
}

// ---------------- residual add + LN (in place on x) ----------------
__global__ void add_ln_kernel(float* __restrict__ x, const float* __restrict__ t,
                              const float* __restrict__ g, const float* __restrict__ bta)
{
    int row = blockIdx.x;
    __shared__ float e[H_];
    __shared__ float sbuf[32];
    float* xr = x + (size_t)row * H_;
    const float* tr = t + (size_t)row * H_;
    float lsum = 0.f, lsq = 0.f;
    for (int j = threadIdx.x; j < H_; j += blockDim.x) {
        float val = xr[j] + tr[j];
        e[j] = val; lsum += val; lsq += val * val;
    }
    float tot = block_reduce_sum(lsum, sbuf);
    float totsq = block_reduce_sum(lsq, sbuf);
    float mean = tot / H_;
    float var  = totsq / H_ - mean * mean;
    float inv  = rsqrtf(var + 1e-5f);
    for (int j = threadIdx.x; j < H_; j += blockDim.x)
        xr[j] = (e[j] - mean) * inv * g[j] + bta[j];
}

// =====================================================================
// Fused flash-attention: 128 q-rows per block, stream K/V in 64-key tiles.
// 256 threads = 8 warps; warp w owns q-rows w*16..w*16+15 (full 64-col width),
// so softmax row reductions stay within a warp (shfl over t-quad).
// Q/K/P fed to tf32 MMA via ldmatrix; V via conflict-free scalar LDS.
// =====================================================================
__global__ void __launch_bounds__(256)
attn_kernel(const float* __restrict__ qkv, const int* __restrict__ seg,
            float* __restrict__ ctx)
{
    extern __shared__ float dsm[];
    float* sP    = dsm;                    // 128*68  (Q staging, then P tiles)
    float* sK    = sP + 128 * 68;          // 2 * 64*68
    float* sV    = sK + 2 * 64 * 68;       // 2 * 64*72
    float* smask = sV + 2 * 64 * 72;       // 512

    const int bh = blockIdx.y;
    const int b = bh / NH_, h = bh - b * NH_;
    const int q0 = blockIdx.x * 128;

    const float* qp = qkv + (size_t)b * S_ * QKVN + h * DH_;
    const float* kp = qp + H_;
    float* cp = ctx + ((size_t)b * S_ + q0) * H_ + h * DH_;

    const int tid = threadIdx.x, lane = tid & 31, wid = tid >> 5;
    const int g = lane >> 2, t = lane & 3;

    for (int i = tid; i < S_; i += 256)
        smask[i] = (seg[b * S_ + i] > 0) ? 0.f : -1e9f;

    // Q tile (128 x 64) -> sP staging
    for (int c = tid; c < 128 * 16; c += 256) {
        int row = c >> 4, kc = (c & 15) << 2;
        cp16(&sP[row * 68 + kc], qp + (size_t)(q0 + row) * QKVN + kc);
    }
    asm volatile("cp.async.commit_group;\n" ::);
    asm volatile("cp.async.wait_group 0;\n" ::);
    __syncthreads();

    const int a_row = wid * 16 + (lane & 7) + ((lane >> 3) & 1) * 8;
    const int a_col = (lane >> 4) * 4;
    uint32_t qf[8][4];
    #pragma unroll
    for (int s = 0; s < 8; s++)
        ldsm4(qf[s], &sP[a_row * 68 + a_col + s * 8]);
    __syncthreads();      // sP free for P use

    auto load_kv = [&](int kt, int buf) {
        int kbase = kt * 64;
        #pragma unroll
        for (int c = tid; c < 64 * 16; c += 256) {
            int row = c >> 4, kc = (c & 15) << 2;
            const float* kg = kp + (size_t)(kbase + row) * QKVN + kc;
            cp16(&sK[buf * 64 * 68 + row * 68 + kc], kg);
            cp16(&sV[buf * 64 * 72 + row * 72 + kc], kg + H_);
        }
        asm volatile("cp.async.commit_group;\n" ::);
    };
    load_kv(0, 0);

    const int b_row = (lane >> 4) * 8 + (lane & 7);
    const int b_col = ((lane >> 3) & 1) * 4;

    float m_run[2] = {-1e30f, -1e30f};
    float l_run[2] = {0.f, 0.f};
    float o[8][4];
    #pragma unroll
    for (int nt = 0; nt < 8; nt++)
        #pragma unroll
        for (int r = 0; r < 4; r++) o[nt][r] = 0.f;

    for (int kt = 0; kt < S_ / 64; kt++) {
        int buf = kt & 1;
        asm volatile("cp.async.wait_group 0;\n" ::);
        __syncthreads();
        if (kt + 1 < S_ / 64) load_kv(kt + 1, buf ^ 1);

        const float* sKb = sK + buf * 64 * 68;
        const float* sVb = sV + buf * 64 * 72;

        // S = Q @ K^T (warp: 16 x 64)
        float sacc[8][4];
        #pragma unroll
        for (int nt = 0; nt < 8; nt++)
            #pragma unroll
            for (int r = 0; r < 4; r++) sacc[nt][r] = 0.f;
        #pragma unroll
        for (int s = 0; s < 8; s++) {
            uint32_t bfr[8][2];
            #pragma unroll
            for (int p = 0; p < 4; p++) {
                uint32_t rr[4];
                ldsm4(rr, &sKb[(b_row + p * 16) * 68 + b_col + s * 8]);
                bfr[2 * p][0] = rr[0]; bfr[2 * p][1] = rr[1];
                bfr[2 * p + 1][0] = rr[2]; bfr[2 * p + 1][1] = rr[3];
            }
            #pragma unroll
            for (int nt = 0; nt < 8; nt++)
                mma_tf32(sacc[nt], qf[s], bfr[nt]);
        }

        // scale + mask + online softmax (rows: g and g+8 of this warp's 16)
        float tmax0 = -1e30f, tmax1 = -1e30f;
        #pragma unroll
        for (int nt = 0; nt < 8; nt++) {
            int col = kt * 64 + nt * 8 + t * 2;
            float mb0 = smask[col], mb1 = smask[col + 1];
            sacc[nt][0] = fmaf(sacc[nt][0], 0.125f, mb0);
            sacc[nt][1] = fmaf(sacc[nt][1], 0.125f, mb1);
            sacc[nt][2] = fmaf(sacc[nt][2], 0.125f, mb0);
            sacc[nt][3] = fmaf(sacc[nt][3], 0.125f, mb1);
            tmax0 = fmaxf(tmax0, fmaxf(sacc[nt][0], sacc[nt][1]));
            tmax1 = fmaxf(tmax1, fmaxf(sacc[nt][2], sacc[nt][3]));
        }
        tmax0 = fmaxf(tmax0, __shfl_xor_sync(0xffffffffu, tmax0, 1));
        tmax0 = fmaxf(tmax0, __shfl_xor_sync(0xffffffffu, tmax0, 2));
        tmax1 = fmaxf(tmax1, __shfl_xor_sync(0xffffffffu, tmax1, 1));
        tmax1 = fmaxf(tmax1, __shfl_xor_sync(0xffffffffu, tmax1, 2));
        float mnew0 = fmaxf(m_run[0], tmax0);
        float mnew1 = fmaxf(m_run[1], tmax1);
        float al0 = __expf(m_run[0] - mnew0);
        float al1 = __expf(m_run[1] - mnew1);
        float ts0 = 0.f, ts1 = 0.f;
        #pragma unroll
        for (int nt = 0; nt < 8; nt++) {
            sacc[nt][0] = __expf(sacc[nt][0] - mnew0);
            sacc[nt][1] = __expf(sacc[nt][1] - mnew0);
            sacc[nt][2] = __expf(sacc[nt][2] - mnew1);
            sacc[nt][3] = __expf(sacc[nt][3] - mnew1);
            ts0 += sacc[nt][0] + sacc[nt][1];
            ts1 += sacc[nt][2] + sacc[nt][3];
        }
        ts0 += __shfl_xor_sync(0xffffffffu, ts0, 1);
        ts0 += __shfl_xor_sync(0xffffffffu, ts0, 2);
        ts1 += __shfl_xor_sync(0xffffffffu, ts1, 1);
        ts1 += __shfl_xor_sync(0xffffffffu, ts1, 2);
        l_run[0] = l_run[0] * al0 + ts0;
        l_run[1] = l_run[1] * al1 + ts1;
        m_run[0] = mnew0; m_run[1] = mnew1;
        #pragma unroll
        for (int nt = 0; nt < 8; nt++) {
            o[nt][0] *= al0; o[nt][1] *= al0;
            o[nt][2] *= al1; o[nt][3] *= al1;
        }

        // write P (own warp rows only), then PV MMA
        float* pw = sP + (wid * 16) * 68;
        #pragma unroll
        for (int nt = 0; nt < 8; nt++) {
            int c0 = nt * 8 + t * 2;
            *(float2*)&pw[g * 68 + c0]       = make_float2(sacc[nt][0], sacc[nt][1]);
            *(float2*)&pw[(g + 8) * 68 + c0] = make_float2(sacc[nt][2], sacc[nt][3]);
        }
        __syncwarp();
        #pragma unroll
        for (int s = 0; s < 8; s++) {
            uint32_t pf[4];
            ldsm4(pf, &sP[a_row * 68 + a_col + s * 8]);
            #pragma unroll
            for (int nt = 0; nt < 8; nt++) {
                uint32_t bf[2];
                bf[0] = __float_as_uint(sVb[(s * 8 + t) * 72 + nt * 8 + g]);
                bf[1] = __float_as_uint(sVb[(s * 8 + t + 4) * 72 + nt * 8 + g]);
                mma_tf32(o[nt], pf, bf);
            }
        }
    }

    float rl0 = 1.f / l_run[0], rl1 = 1.f / l_run[1];
    int r0 = wid * 16 + g;
    #pragma unroll
    for (int nt = 0; nt < 8; nt++) {
        int col = nt * 8 + t * 2;
        float2 v0 = make_float2(__uint_as_float(f2tf32(o[nt][0] * rl0)),
                                __uint_as_float(f2tf32(o[nt][1] * rl0)));
        float2 v1 = make_float2(__uint_as_float(f2tf32(o[nt][2] * rl1)),
                                __uint_as_float(f2tf32(o[nt][3] * rl1)));
        *(float2*)&cp[(size_t)r0 * H_ + col]       = v0;
        *(float2*)&cp[(size_t)(r0 + 8) * H_ + col] = v1;
    }
}

// =====================================================================
// TF32 tensor-core GEMM, BM=128, BN=128, BK=16, ldmatrix feed, 3-stage.
// 8 warps: wm=wid&3 (32 rows), wn=wid>>2 (64 cols). B gmem is [N][K].
// REQUIRES M%128==0, N%128==0, K%16==0.
// =====================================================================
template<int CVT_A, int ACT, int OTF>
__global__ void __launch_bounds__(256)
mma_gemm(const float* __restrict__ A, const float* __restrict__ Bm,
         const float* __restrict__ bias, float* __restrict__ C,
         int K, int lda, int ldb, int ldc)
{
    extern __shared__ float dsm[];
    float* As = dsm;                 // [3][128*20]
    float* Bs = dsm + 3 * 128 * 20;  // [3][128*20]

    const int m0  = blockIdx.y * 128;
    const int n0  = blockIdx.x * 128;
    const int tid = threadIdx.x;
    const int lane = tid & 31, wid = tid >> 5;
    const int wm = wid & 3, wn = wid >> 2;
    const int g = lane >> 2, t = lane & 3;

    const int a_row = wm * 32 + (lane & 7) + ((lane >> 3) & 1) * 8;  // +mt*16
    const int a_col = (lane >> 4) * 4;
    const int b_row = wn * 64 + (lane >> 4) * 8 + (lane & 7);        // +p*16
    const int b_col = ((lane >> 3) & 1) * 4;

    const int ntiles = K >> 4;

    auto copy_tile = [&](int kt, int buf) {
        int k0 = kt << 4;
        float* ab = As + buf * 2560;
        float* bb = Bs + buf * 2560;
        #pragma unroll
        for (int c = tid; c < 512; c += 256) {
            int row = c >> 2, kc = (c & 3) << 2;
            cp16(&ab[row * 20 + kc], A + (long)(m0 + row) * lda + k0 + kc);
        }
        #pragma unroll
        for (int c = tid; c < 512; c += 256) {
            int row = c >> 2, kc = (c & 3) << 2;
            cp16(&bb[row * 20 + kc], Bm + (long)(n0 + row) * ldb + k0 + kc);
        }
        asm volatile("cp.async.commit_group;\n" ::);
    };

    float acc[2][8][4];
    #pragma unroll
    for (int i = 0; i < 2; i++)
        #pragma unroll
        for (int j = 0; j < 8; j++)
            #pragma unroll
            for (int r = 0; r < 4; r++) acc[i][j][r] = 0.f;

    copy_tile(0, 0);
    if (ntiles > 1) copy_tile(1, 1);

    for (int kt = 0; kt < ntiles; kt++) {
        int buf = kt % 3;
        if (kt + 2 < ntiles) {
            asm volatile("cp.async.wait_group 1;\n" ::);
        } else {
            asm volatile("cp.async.wait_group 0;\n" ::);
        }
        __syncthreads();
        if (kt + 2 < ntiles) copy_tile(kt + 2, (kt + 2) % 3);

        const float* ab = As + buf * 2560;
        const float* bb = Bs + buf * 2560;

        #pragma unroll
        for (int ks = 0; ks < 16; ks += 8) {
            uint32_t afr[2][4];
            #pragma unroll
            for (int mt = 0; mt < 2; mt++) {
                ldsm4(afr[mt], &ab[(a_row + mt * 16) * 20 + a_col + ks]);
                if (CVT_A) {
                    #pragma unroll
                    for (int r = 0; r < 4; r++)
                        afr[mt][r] = f2tf32(__uint_as_float(afr[mt][r]));
                }
            }
            uint32_t bfr[8][2];
            #pragma unroll
            for (int p = 0; p < 4; p++) {
                uint32_t rr[4];
                ldsm4(rr, &bb[(b_row + p * 16) * 20 + b_col + ks]);
                bfr[2 * p][0] = rr[0]; bfr[2 * p][1] = rr[1];
                bfr[2 * p + 1][0] = rr[2]; bfr[2 * p + 1][1] = rr[3];
            }
            #pragma unroll
            for (int mt = 0; mt < 2; mt++)
                #pragma unroll
                for (int nt = 0; nt < 8; nt++)
                    mma_tf32(acc[mt][nt], afr[mt], bfr[nt]);
        }
        __syncthreads();
    }

    #pragma unroll
    for (int mt = 0; mt < 2; mt++) {
        #pragma unroll
        for (int nt = 0; nt < 8; nt++) {
            int row = m0 + wm * 32 + mt * 16 + g;
            int col = n0 + wn * 64 + nt * 8 + t * 2;
            float bv0 = 0.f, bv1 = 0.f;
            if (bias) { bv0 = bias[col]; bv1 = bias[col + 1]; }
            #pragma unroll
            for (int half = 0; half < 2; half++) {
                int r = row + half * 8;
                float v0 = acc[mt][nt][half * 2 + 0] + bv0;
                float v1 = acc[mt][nt][half * 2 + 1] + bv1;
                if (ACT == 1) { v0 = gelu_tanh(v0); v1 = gelu_tanh(v1); }
                if (OTF) {
                    v0 = __uint_as_float(f2tf32(v0));
                    v1 = __uint_as_float(f2tf32(v1));
                }
                *(float2*)&C[(long)r * ldc + col] = make_float2(v0, v1);
            }
        }
    }
}

// ---------------- small SIMT GEMM (pooler + classifier only) ----------------
template<int ACT> // 0 none, 2 tanh
__global__ void gemm_kernel(const float* __restrict__ A, const float* __restrict__ Bm,
                            const float* __restrict__ bias, float* __restrict__ C,
                            int M, int N, int K, int lda, int ldb, int ldc)
{
    __shared__ float As[16][65];
    __shared__ float Bs[16][65];

    int m0 = blockIdx.y * 64;
    int n0 = blockIdx.x * 64;
    int tid = threadIdx.x;
    int tx = tid & 15, ty = tid >> 4;

    float acc[4][4] = {};

    for (int k0 = 0; k0 < K; k0 += 16) {
        #pragma unroll
        for (int i = tid; i < 64 * 16; i += 256) {
            int m = i >> 4, k = i & 15;
            int gm = m0 + m, gk = k0 + k;
            As[k][m] = (gm < M && gk < K) ? A[(long)gm * lda + gk] : 0.f;
        }
        #pragma unroll
        for (int i = tid; i < 16 * 64; i += 256) {
            int k = i >> 6, n = i & 63;
            int gk = k0 + k, gn = n0 + n;
            Bs[k][n] = (gk < K && gn < N) ? Bm[(long)gk * ldb + gn] : 0.f;
        }
        __syncthreads();
        #pragma unroll
        for (int k = 0; k < 16; k++) {
            float a[4], bb[4];
            #pragma unroll
            for (int i = 0; i < 4; i++) a[i] = As[k][ty * 4 + i];
            #pragma unroll
            for (int j = 0; j < 4; j++) bb[j] = Bs[k][tx * 4 + j];
            #pragma unroll
            for (int i = 0; i < 4; i++)
                #pragma unroll
                for (int j = 0; j < 4; j++)
                    acc[i][j] = fmaf(a[i], bb[j], acc[i][j]);
        }
        __syncthreads();
    }

    #pragma unroll
    for (int i = 0; i < 4; i++) {
        int gm = m0 + ty * 4 + i;
        if (gm >= M) continue;
        #pragma unroll
        for (int j = 0; j < 4; j++) {
            int gn = n0 + tx * 4 + j;
            if (gn >= N) continue;
            float v = acc[i][j];
            if (bias) v += bias[gn];
            if (ACT == 2) v = tanhf(v);
            C[(long)gm * ldc + gn] = v;
        }
    }
}

// ---------------- log-softmax + NLL loss + output write ----------------
__global__ void loss_kernel(const float* __restrict__ logits, const int* __restrict__ tgt,
                            float* __restrict__ out, int out_size)
{
    int lane = threadIdx.x;
    float lp = 0.f;
    if (lane < B_) {
        const float* row = logits + lane * LAB_;
        float mx = row[0];
        #pragma unroll
        for (int j = 1; j < LAB_; j++) mx = fmaxf(mx, row[j]);
        float s = 0.f;
        #pragma unroll
        for (int j = 0; j < LAB_; j++) s += expf(row[j] - mx);
        lp = row[tgt[lane]] - mx - logf(s);
    }
    #pragma unroll
    for (int o = 16; o; o >>= 1) lp += __shfl_down_sync(0xffffffffu, lp, o);
    int ofs = (out_size > B_ * LAB_) ? 1 : 0;
    if (lane == 0 && ofs) out[0] = -lp / (float)B_;
    for (int i = lane; i < B_ * LAB_; i += 32) out[ofs + i] = logits[i];
}

// ---------------- host launch ----------------
#define GEMM_SMEM  (3 * 128 * 20 * 2 * 4)                       // 61440
#define ATTN_SMEM  ((128*68 + 2*64*68 + 2*64*72 + 512) * 4)     // 108544

extern "C" void kernel_launch(void* const* d_in, const int* in_sizes, int n_in,
                              void* d_out, int out_size)
{
    const int*   src  = (const int*)d_in[0];
    const int*   seg  = (const int*)d_in[1];
    const int*   tgt  = (const int*)d_in[2];
    const int*   tib  = (const int*)d_in[3];
    const float* we   = (const float*)d_in[4];
    const float* pe   = (const float*)d_in[5];
    const float* se   = (const float*)d_in[6];
    const float* elng = (const float*)d_in[7];
    const float* elnb = (const float*)d_in[8];
    const float* Wq   = (const float*)d_in[9];
    const float* bq   = (const float*)d_in[10];
    const float* Wk   = (const float*)d_in[11];
    const float* bk   = (const float*)d_in[12];
    const float* Wv   = (const float*)d_in[13];
    const float* bv   = (const float*)d_in[14];
    const float* Wo   = (const float*)d_in[15];
    const float* bo   = (const float*)d_in[16];
    const float* ln1g = (const float*)d_in[17];
    const float* ln1b = (const float*)d_in[18];
    const float* Wf1  = (const float*)d_in[19];
    const float* bf1  = (const float*)d_in[20];
    const float* Wf2  = (const float*)d_in[21];
    const float* bf2  = (const float*)d_in[22];
    const float* ln2g = (const float*)d_in[23];
    const float* ln2b = (const float*)d_in[24];
    const float* Wp1  = (const float*)d_in[25];
    const float* bp1  = (const float*)d_in[26];
    const float* Wp2  = (const float*)d_in[27];
    const float* bp2  = (const float*)d_in[28];
    const float* sel  = (const float*)d_in[29];
    (void)in_sizes; (void)n_in;

    float *x, *qkv, *ctx, *tmp, *ff, *hidden, *logits;
    float *wqkvT, *woT, *wf1T, *wf2T, *bqkv;
    cudaGetSymbolAddress((void**)&x,     g_x);
    cudaGetSymbolAddress((void**)&qkv,   g_qkv);
    cudaGetSymbolAddress((void**)&ctx,   g_ctx);
    cudaGetSymbolAddress((void**)&tmp,   g_tmp);
    cudaGetSymbolAddress((void**)&ff,    g_ff);
    cudaGetSymbolAddress((void**)&hidden,g_hidden);
    cudaGetSymbolAddress((void**)&logits,g_logits);
    cudaGetSymbolAddress((void**)&wqkvT, g_wqkvT);
    cudaGetSymbolAddress((void**)&woT,   g_woT);
    cudaGetSymbolAddress((void**)&wf1T,  g_wf1T);
    cudaGetSymbolAddress((void**)&wf2T,  g_wf2T);
    cudaGetSymbolAddress((void**)&bqkv,  g_bqkv);

    cudaFuncSetAttribute(mma_gemm<1,0,1>, cudaFuncAttributeMaxDynamicSharedMemorySize, GEMM_SMEM);
    cudaFuncSetAttribute(mma_gemm<0,0,0>, cudaFuncAttributeMaxDynamicSharedMemorySize, GEMM_SMEM);
    cudaFuncSetAttribute(mma_gemm<1,1,1>, cudaFuncAttributeMaxDynamicSharedMemorySize, GEMM_SMEM);
    cudaFuncSetAttribute(attn_kernel,     cudaFuncAttributeMaxDynamicSharedMemorySize, ATTN_SMEM);

    const int Mtok = B_ * S_;                    // 8192
    dim3 blk(256);

    // weight prep: transposes + tf32 rounding, bias concat
    {
        dim3 tb(32, 8);
        dim3 gHH(H_ / 32, H_ / 32, L_);
        transpose_cvt<<<gHH, tb>>>(Wq, wqkvT,                 H_, H_, (long)QKVN * H_);
        transpose_cvt<<<gHH, tb>>>(Wk, wqkvT + (size_t)H_*H_, H_, H_, (long)QKVN * H_);
        transpose_cvt<<<gHH, tb>>>(Wv, wqkvT + (size_t)2*H_*H_, H_, H_, (long)QKVN * H_);
        transpose_cvt<<<gHH, tb>>>(Wo, woT, H_, H_, (long)H_ * H_);
        dim3 gF1(FF_ / 32, H_ / 32, L_);
        transpose_cvt<<<gF1, tb>>>(Wf1, wf1T, H_, FF_, (long)FF_ * H_);
        dim3 gF2(H_ / 32, FF_ / 32, L_);
        transpose_cvt<<<gF2, tb>>>(Wf2, wf2T, FF_, H_, (long)H_ * FF_);
        concat_bias<<<(L_ * QKVN + 255) / 256, 256>>>(bq, bk, bv, bqkv);
    }

    embed_kernel<<<Mtok, 256>>>(src, seg, tib, we, pe, se, elng, elnb, sel, x);

    dim3 gQKV(QKVN / 128, Mtok / 128);   // (18, 64)
    dim3 gH  (H_   / 128, Mtok / 128);   // (6, 64)
    dim3 gFF (FF_  / 128, Mtok / 128);   // (24, 64)
    dim3 gAtt(S_ / 128, B_ * NH_);       // (4, 192)

    for (int l = 0; l < L_; l++) {
        const float* wqkv = wqkvT + (size_t)l * QKVN * H_;
        const float* wo   = woT   + (size_t)l * H_ * H_;
        const float* wf1  = wf1T  + (size_t)l * H_ * FF_;
        const float* wf2  = wf2T  + (size_t)l * FF_ * H_;

        mma_gemm<1,0,1><<<gQKV, blk, GEMM_SMEM>>>(x, wqkv, bqkv + l * QKVN, qkv,
                                                  H_, H_, H_, QKVN);
        attn_kernel<<<gAtt, blk, ATTN_SMEM>>>(qkv, seg, ctx);
        mma_gemm<0,0,0><<<gH, blk, GEMM_SMEM>>>(ctx, wo, bo + l * H_, tmp,
                                                H_, H_, H_, H_);
        add_ln_kernel<<<Mtok, 256>>>(x, tmp, ln1g + l * H_, ln1b + l * H_);

        mma_gemm<1,1,1><<<gFF, blk, GEMM_SMEM>>>(x, wf1, bf1 + l * FF_, ff,
                                                 H_, H_, H_, FF_);
        mma_gemm<0,0,0><<<gH, blk, GEMM_SMEM>>>(ff, wf2, bf2 + l * H_, tmp,
                                                FF_, FF_, FF_, H_);
        add_ln_kernel<<<Mtok, 256>>>(x, tmp, ln2g + l * H_, ln2b + l * H_);
    }

    dim3 gPool((H_ + 63) / 64, 1);
    gemm_kernel<2><<<gPool, blk>>>(x, Wp1, bp1, hidden, B_, H_, H_,
                                   S_ * H_, H_, H_);
    dim3 gCls(1, 1);
    gemm_kernel<0><<<gCls, blk>>>(hidden, Wp2, bp2, logits, B_, LAB_, H_,
                                  H_, LAB_, LAB_);

    loss_kernel<<<1, 32>>>(logits, tgt, (float*)d_out, out_size);
}

// round 6
// speedup vs baseline: 13.8655x; 1.8481x over previous
#include <cuda_runtime.h>
#include <cuda_fp16.h>
#include <math.h>
#include <stdint.h>

#define B_   16
#define S_   512
#define H_   768
#define NH_  12
#define L_   6
#define FF_  3072
#define DH_  64
#define LAB_ 10
#define QKVN 2304          // 3*H

// ---------------- scratch (device globals; no allocations allowed) ----------
__device__ float  g_x   [(size_t)B_*S_*H_];
__device__ __half g_xh  [(size_t)B_*S_*H_];
__device__ __half g_qkv [(size_t)B_*S_*QKVN];
__device__ __half g_ctxh[(size_t)B_*S_*H_];
__device__ float  g_tmp [(size_t)B_*S_*H_];
__device__ __half g_ffh [(size_t)B_*S_*FF_];
__device__ float  g_hidden[(size_t)B_*H_];
__device__ float  g_logits[(size_t)B_*LAB_];
// transposed + fp16 weights [N][K]
__device__ __half g_wqkvT[(size_t)L_*QKVN*H_];
__device__ __half g_woT  [(size_t)L_*H_*H_];
__device__ __half g_wf1T [(size_t)L_*FF_*H_];
__device__ __half g_wf2T [(size_t)L_*H_*FF_];
__device__ float  g_bqkv [(size_t)L_*QKVN];

// ---------------- small helpers ----------------
__device__ __forceinline__ uint32_t smem_u32(const void* p) {
    return (uint32_t)__cvta_generic_to_shared(p);
}

__device__ __forceinline__ void cp16s(uint32_t s, const void* g) {
    asm volatile("cp.async.ca.shared.global [%0], [%1], 16;\n" :: "r"(s), "l"(g));
}

__device__ __forceinline__ void ldsm4(uint32_t* r, uint32_t a) {
    asm volatile("ldmatrix.sync.aligned.m8n8.x4.shared.b16 {%0,%1,%2,%3}, [%4];"
                 : "=r"(r[0]), "=r"(r[1]), "=r"(r[2]), "=r"(r[3]) : "r"(a));
}

__device__ __forceinline__ void ldsm4t(uint32_t* r, uint32_t a) {
    asm volatile("ldmatrix.sync.aligned.m8n8.x4.trans.shared.b16 {%0,%1,%2,%3}, [%4];"
                 : "=r"(r[0]), "=r"(r[1]), "=r"(r[2]), "=r"(r[3]) : "r"(a));
}

__device__ __forceinline__ void mma_f16(float* c, const uint32_t* a, const uint32_t* b) {
    asm volatile(
        "mma.sync.aligned.m16n8k16.row.col.f32.f16.f16.f32 "
        "{%0,%1,%2,%3}, {%4,%5,%6,%7}, {%8,%9}, {%0,%1,%2,%3};\n"
        : "+f"(c[0]), "+f"(c[1]), "+f"(c[2]), "+f"(c[3])
        : "r"(a[0]), "r"(a[1]), "r"(a[2]), "r"(a[3]), "r"(b[0]), "r"(b[1]));
}

__device__ __forceinline__ float gelu_tanh(float v) {
    float c = v * v * v;
    return 0.5f * v * (1.f + tanhf(0.7978845608028654f * (v + 0.044715f * c)));
}

// ---------------- block reductions ----------------
__device__ __forceinline__ float block_reduce_sum(float v, float* sbuf) {
    __syncthreads();
    #pragma unroll
    for (int o = 16; o; o >>= 1) v += __shfl_down_sync(0xffffffffu, v, o);
    int lane = threadIdx.x & 31, w = threadIdx.x >> 5;
    if (lane == 0) sbuf[w] = v;
    __syncthreads();
    if (w == 0) {
        int nw = (blockDim.x + 31) >> 5;
        v = (lane < nw) ? sbuf[lane] : 0.f;
        #pragma unroll
        for (int o = 16; o; o >>= 1) v += __shfl_down_sync(0xffffffffu, v, o);
        if (lane == 0) sbuf[0] = v;
    }
    __syncthreads();
    return sbuf[0];
}

// ---------------- weight transpose + fp16 convert ----------------
__global__ void transpose_cvt(const float* __restrict__ in, __half* __restrict__ out,
                              int R, int C, long ozs)
{
    in  += (size_t)blockIdx.z * R * C;
    out += (size_t)blockIdx.z * ozs;
    __shared__ float t[32][33];
    int c0 = blockIdx.x * 32, r0 = blockIdx.y * 32;
    int tx = threadIdx.x, ty = threadIdx.y;
    #pragma unroll
    for (int i = 0; i < 32; i += 8)
        t[ty + i][tx] = in[(size_t)(r0 + ty + i) * C + c0 + tx];
    __syncthreads();
    #pragma unroll
    for (int i = 0; i < 32; i += 8)
        out[(size_t)(c0 + ty + i) * R + r0 + tx] = __float2half_rn(t[tx][ty + i]);
}

__global__ void concat_bias(const float* __restrict__ bq, const float* __restrict__ bk,
                            const float* __restrict__ bv, float* __restrict__ out)
{
    int i = blockIdx.x * 256 + threadIdx.x;
    if (i >= L_ * QKVN) return;
    int l = i / QKVN, r = i - l * QKVN;
    float val;
    if (r < H_)            val = bq[l * H_ + r];
    else if (r < 2 * H_)   val = bk[l * H_ + r - H_];
    else                   val = bv[l * H_ + r - 2 * H_];
    out[i] = val;
}

// ---------------- embedding + LN + selection ----------------
__global__ void embed_kernel(const int* __restrict__ src, const int* __restrict__ seg,
                             const int* __restrict__ tib,
                             const float* __restrict__ we, const float* __restrict__ pe,
                             const float* __restrict__ se,
                             const float* __restrict__ g, const float* __restrict__ bta,
                             const float* __restrict__ sel, float* __restrict__ x,
                             __half* __restrict__ xh)
{
    int t = blockIdx.x;
    int s = t % S_;
    __shared__ float e[H_];
    __shared__ float sbuf[32];
    int w = src[t], sg = seg[t];
    const float* wr = we + (size_t)w * H_;
    const float* pr = pe + (size_t)s * H_;
    const float* sr = se + (size_t)sg * H_;
    float lsum = 0.f, lsq = 0.f;
    for (int j = threadIdx.x; j < H_; j += blockDim.x) {
        float val = wr[j] + pr[j] + sr[j];
        e[j] = val; lsum += val; lsq += val * val;
    }
    float tot = block_reduce_sum(lsum, sbuf);
    float totsq = block_reduce_sum(lsq, sbuf);
    float mean = tot / H_;
    float var  = totsq / H_ - mean * mean;
    float inv  = rsqrtf(var + 1e-5f);
    float f = sel[tib[t]];
    float* xo = x + (size_t)t * H_;
    __half* xho = xh + (size_t)t * H_;
    for (int j = threadIdx.x; j < H_; j += blockDim.x) {
        float val = ((e[j] - mean) * inv * g[j] + bta[j]) * f;
        xo[j] = val;
        xho[j] = __float2half_rn(val);
    }
}

// ---------------- residual add + LN (in place on x, writes half copy) -------
__global__ void add_ln_kernel(float* __restrict__ x, const float* __restrict__ t,
                              const float* __restrict__ g, const float* __restrict__ bta,
                              __half* __restrict__ xh)
{
    int row = blockIdx.x;
    __shared__ float e[H_];
    __shared__ float sbuf[32];
    float* xr = x + (size_t)row * H_;
    __half* xhr = xh + (size_t)row * H_;
    const float* tr = t + (size_t)row * H_;
    float lsum = 0.f, lsq = 0.f;
    for (int j = threadIdx.x; j < H_; j += blockDim.x) {
        float val = xr[j] + tr[j];
        e[j] = val; lsum += val; lsq += val * val;
    }
    float tot = block_reduce_sum(lsum, sbuf);
    float totsq = block_reduce_sum(lsq, sbuf);
    float mean = tot / H_;
    float var  = totsq / H_ - mean * mean;
    float inv  = rsqrtf(var + 1e-5f);
    for (int j = threadIdx.x; j < H_; j += blockDim.x) {
        float val = (e[j] - mean) * inv * g[j] + bta[j];
        xr[j] = val;
        xhr[j] = __float2half_rn(val);
    }
}

// =====================================================================
// FP16 tensor-core GEMM: out = act(A[M,K] @ Bw[N,K]^T + bias)
// BM=128, BN=128, BK=32 halves. 256 threads = 8 warps (wm 0..3, wn 0..1),
// warp tile 32x64, m16n8k16 mma, 3-stage cp.async, row stride 40 halves (80B).
// ACT: 0 none, 1 gelu. OUTH: 1 -> write __half, 0 -> write float.
// =====================================================================
#define HG_SMEM 61440

template<int ACT, int OUTH>
__global__ void __launch_bounds__(256)
hgemm(const __half* __restrict__ A, const __half* __restrict__ Bw,
      const float* __restrict__ bias, void* __restrict__ Cout,
      int K, int lda, int ldb, int ldc)
{
    extern __shared__ char smem[];
    const uint32_t sb = smem_u32(smem);
    const uint32_t A_OFF = 0, B_OFF = 30720;   // 3 stages * 10240B each

    const int m0  = blockIdx.y * 128;
    const int n0  = blockIdx.x * 128;
    const int tid = threadIdx.x;
    const int lane = tid & 31, wid = tid >> 5;
    const int wm = wid & 3, wn = wid >> 2;
    const int g = lane >> 2, t = lane & 3;

    // ldmatrix byte offsets (within a stage, before ks offset)
    const uint32_t a_base = (uint32_t)(wm * 32 + (lane & 15)) * 80 + ((lane >> 4) << 4);
    const uint32_t b_base = (uint32_t)(wn * 64 + ((lane >> 4) << 3) + (lane & 7)) * 80
                          + (((lane >> 3) & 1) << 4);

    const int nt = K >> 5;

    auto load_st = [&](int kt) {
        int st = kt % 3;
        int k0 = kt << 5;
        uint32_t ab = sb + A_OFF + st * 10240;
        uint32_t bb = sb + B_OFF + st * 10240;
        #pragma unroll
        for (int i = 0; i < 2; i++) {
            int c = i * 256 + tid;              // 512 chunks each operand
            int row = c >> 2, kc = (c & 3) << 3;
            uint32_t d = (uint32_t)(c >> 2) * 80 + ((c & 3) << 4);
            cp16s(ab + d, A  + (size_t)(m0 + row) * lda + k0 + kc);
            cp16s(bb + d, Bw + (size_t)(n0 + row) * ldb + k0 + kc);
        }
        asm volatile("cp.async.commit_group;" ::: "memory");
    };

    float acc[2][8][4];
    #pragma unroll
    for (int i = 0; i < 2; i++)
        #pragma unroll
        for (int j = 0; j < 8; j++)
            #pragma unroll
            for (int r = 0; r < 4; r++) acc[i][j][r] = 0.f;

    load_st(0);
    if (nt > 1) load_st(1);

    for (int kt = 0; kt < nt; kt++) {
        int st = kt % 3;
        if (kt + 2 < nt)
            asm volatile("cp.async.wait_group 1;" ::: "memory");
        else
            asm volatile("cp.async.wait_group 0;" ::: "memory");
        __syncthreads();
        if (kt + 2 < nt) load_st(kt + 2);

        uint32_t ab = sb + A_OFF + st * 10240;
        uint32_t bb = sb + B_OFF + st * 10240;

        #pragma unroll
        for (int ks = 0; ks < 2; ks++) {
            uint32_t afr[2][4];
            #pragma unroll
            for (int mt = 0; mt < 2; mt++)
                ldsm4(afr[mt], ab + a_base + mt * (16 * 80) + ks * 32);
            uint32_t bfr[8][2];
            #pragma unroll
            for (int p = 0; p < 4; p++) {
                uint32_t rr[4];
                ldsm4(rr, bb + b_base + p * (16 * 80) + ks * 32);
                bfr[2 * p][0]     = rr[0]; bfr[2 * p][1]     = rr[1];
                bfr[2 * p + 1][0] = rr[2]; bfr[2 * p + 1][1] = rr[3];
            }
            #pragma unroll
            for (int mt = 0; mt < 2; mt++)
                #pragma unroll
                for (int ntl = 0; ntl < 8; ntl++)
                    mma_f16(acc[mt][ntl], afr[mt], bfr[ntl]);
        }
        __syncthreads();
    }

    #pragma unroll
    for (int mt = 0; mt < 2; mt++) {
        #pragma unroll
        for (int ntl = 0; ntl < 8; ntl++) {
            int row = m0 + wm * 32 + mt * 16 + g;
            int col = n0 + wn * 64 + ntl * 8 + t * 2;
            float bv0 = bias[col], bv1 = bias[col + 1];
            #pragma unroll
            for (int half_ = 0; half_ < 2; half_++) {
                int r = row + half_ * 8;
                float v0 = acc[mt][ntl][half_ * 2 + 0] + bv0;
                float v1 = acc[mt][ntl][half_ * 2 + 1] + bv1;
                if (ACT == 1) { v0 = gelu_tanh(v0); v1 = gelu_tanh(v1); }
                if (OUTH) {
                    __half2* C = (__half2*)((__half*)Cout + (size_t)r * ldc + col);
                    *C = __floats2half2_rn(v0, v1);
                } else {
                    float* C = (float*)Cout + (size_t)r * ldc + col;
                    *(float2*)C = make_float2(v0, v1);
                }
            }
        }
    }
}

// =====================================================================
// Fused flash-attention, fp16 operands / fp32 softmax+accum.
// 128 q-rows per block; warp w owns q-rows w*16..w*16+15 across 64 cols.
// smem rows: 64 halves + 8 pad = stride 72 halves (144B, ldsm conflict-free).
// =====================================================================
#define ATTN_SMEM  ((128*72 + 2*64*72 + 2*64*72) * 2 + 512 * 4)   // 57344

__global__ void __launch_bounds__(256)
attn_kernel(const __half* __restrict__ qkv, const int* __restrict__ seg,
            __half* __restrict__ ctx)
{
    extern __shared__ __half hsm[];
    __half* sP    = hsm;                       // 128*72 (Q staging, then P)
    __half* sK    = sP + 128 * 72;             // 2 * 64*72
    __half* sV    = sK + 2 * 64 * 72;          // 2 * 64*72
    float*  smask = (float*)(sV + 2 * 64 * 72);

    const int bh = blockIdx.y;
    const int b = bh / NH_, h = bh - b * NH_;
    const int q0 = blockIdx.x * 128;

    const __half* qp = qkv + (size_t)b * S_ * QKVN + h * DH_;
    const __half* kp = qp + H_;
    __half* cp = ctx + ((size_t)b * S_ + q0) * H_ + h * DH_;

    const int tid = threadIdx.x, lane = tid & 31, wid = tid >> 5;
    const int g = lane >> 2, t = lane & 3;
    const uint32_t sPb = smem_u32(sP);
    const uint32_t sKb0 = smem_u32(sK);
    const uint32_t sVb0 = smem_u32(sV);

    for (int i = tid; i < S_; i += 256)
        smask[i] = (seg[b * S_ + i] > 0) ? 0.f : -1e9f;

    // Q tile 128 x 64 halves -> sP
    #pragma unroll
    for (int i = 0; i < 4; i++) {
        int c = i * 256 + tid;                 // 1024 chunks
        int row = c >> 3, kc = (c & 7) << 3;
        cp16s(sPb + (uint32_t)row * 144 + ((c & 7) << 4),
              qp + (size_t)(q0 + row) * QKVN + kc);
    }
    asm volatile("cp.async.commit_group;" ::: "memory");
    asm volatile("cp.async.wait_group 0;" ::: "memory");
    __syncthreads();

    const uint32_t a_base = (uint32_t)(wid * 16 + (lane & 15)) * 144 + ((lane >> 4) << 4);
    uint32_t qf[4][4];
    #pragma unroll
    for (int s = 0; s < 4; s++)
        ldsm4(qf[s], sPb + a_base + s * 32);
    __syncthreads();      // sP now free for P

    auto load_kv = [&](int kt, int buf) {
        int kbase = kt * 64;
        #pragma unroll
        for (int i = 0; i < 2; i++) {
            int c = i * 256 + tid;             // 512 chunks
            int row = c >> 3, kc = (c & 7) << 3;
            const __half* kg = kp + (size_t)(kbase + row) * QKVN + kc;
            uint32_t d = (uint32_t)row * 144 + ((c & 7) << 4);
            cp16s(sKb0 + buf * 9216 + d, kg);       // 64*144 = 9216 bytes
            cp16s(sVb0 + buf * 9216 + d, kg + H_);
        }
        asm volatile("cp.async.commit_group;" ::: "memory");
    };
    load_kv(0, 0);

    // K as B-operand (non-trans): rows = keys [n][k]
    const uint32_t bK_base = (uint32_t)(((lane >> 4) << 3) + (lane & 7)) * 144
                           + (((lane >> 3) & 1) << 4);
    // V as B-operand (trans): rows = keys [k][n]
    const uint32_t bV_base = (uint32_t)(lane & 15) * 144 + (((lane >> 4) & 1) << 4);

    float m_run[2] = {-1e30f, -1e30f};
    float l_run[2] = {0.f, 0.f};
    float o[8][4];
    #pragma unroll
    for (int ntl = 0; ntl < 8; ntl++)
        #pragma unroll
        for (int r = 0; r < 4; r++) o[ntl][r] = 0.f;

    for (int kt = 0; kt < S_ / 64; kt++) {
        int buf = kt & 1;
        asm volatile("cp.async.wait_group 0;" ::: "memory");
        __syncthreads();
        if (kt + 1 < S_ / 64) load_kv(kt + 1, buf ^ 1);

        uint32_t sKb = sKb0 + buf * 9216;
        uint32_t sVb = sVb0 + buf * 9216;

        // S = Q @ K^T : warp tile 16 x 64, K-dim 64 (4 ks-steps)
        float sacc[8][4];
        #pragma unroll
        for (int ntl = 0; ntl < 8; ntl++)
            #pragma unroll
            for (int r = 0; r < 4; r++) sacc[ntl][r] = 0.f;
        #pragma unroll
        for (int s = 0; s < 4; s++) {
            uint32_t bfr[8][2];
            #pragma unroll
            for (int p = 0; p < 4; p++) {
                uint32_t rr[4];
                ldsm4(rr, sKb + bK_base + p * (16 * 144) + s * 32);
                bfr[2 * p][0]     = rr[0]; bfr[2 * p][1]     = rr[1];
                bfr[2 * p + 1][0] = rr[2]; bfr[2 * p + 1][1] = rr[3];
            }
            #pragma unroll
            for (int ntl = 0; ntl < 8; ntl++)
                mma_f16(sacc[ntl], qf[s], bfr[ntl]);
        }

        // scale + mask + online softmax
        float tmax0 = -1e30f, tmax1 = -1e30f;
        #pragma unroll
        for (int ntl = 0; ntl < 8; ntl++) {
            int col = kt * 64 + ntl * 8 + t * 2;
            float mb0 = smask[col], mb1 = smask[col + 1];
            sacc[ntl][0] = fmaf(sacc[ntl][0], 0.125f, mb0);
            sacc[ntl][1] = fmaf(sacc[ntl][1], 0.125f, mb1);
            sacc[ntl][2] = fmaf(sacc[ntl][2], 0.125f, mb0);
            sacc[ntl][3] = fmaf(sacc[ntl][3], 0.125f, mb1);
            tmax0 = fmaxf(tmax0, fmaxf(sacc[ntl][0], sacc[ntl][1]));
            tmax1 = fmaxf(tmax1, fmaxf(sacc[ntl][2], sacc[ntl][3]));
        }
        tmax0 = fmaxf(tmax0, __shfl_xor_sync(0xffffffffu, tmax0, 1));
        tmax0 = fmaxf(tmax0, __shfl_xor_sync(0xffffffffu, tmax0, 2));
        tmax1 = fmaxf(tmax1, __shfl_xor_sync(0xffffffffu, tmax1, 1));
        tmax1 = fmaxf(tmax1, __shfl_xor_sync(0xffffffffu, tmax1, 2));
        float mnew0 = fmaxf(m_run[0], tmax0);
        float mnew1 = fmaxf(m_run[1], tmax1);
        float al0 = __expf(m_run[0] - mnew0);
        float al1 = __expf(m_run[1] - mnew1);
        float ts0 = 0.f, ts1 = 0.f;
        #pragma unroll
        for (int ntl = 0; ntl < 8; ntl++) {
            sacc[ntl][0] = __expf(sacc[ntl][0] - mnew0);
            sacc[ntl][1] = __expf(sacc[ntl][1] - mnew0);
            sacc[ntl][2] = __expf(sacc[ntl][2] - mnew1);
            sacc[ntl][3] = __expf(sacc[ntl][3] - mnew1);
            ts0 += sacc[ntl][0] + sacc[ntl][1];
            ts1 += sacc[ntl][2] + sacc[ntl][3];
        }
        ts0 += __shfl_xor_sync(0xffffffffu, ts0, 1);
        ts0 += __shfl_xor_sync(0xffffffffu, ts0, 2);
        ts1 += __shfl_xor_sync(0xffffffffu, ts1, 1);
        ts1 += __shfl_xor_sync(0xffffffffu, ts1, 2);
        l_run[0] = l_run[0] * al0 + ts0;
        l_run[1] = l_run[1] * al1 + ts1;
        m_run[0] = mnew0; m_run[1] = mnew1;
        #pragma unroll
        for (int ntl = 0; ntl < 8; ntl++) {
            o[ntl][0] *= al0; o[ntl][1] *= al0;
            o[ntl][2] *= al1; o[ntl][3] *= al1;
        }

        // write P (fp16, own warp rows), then P @ V
        __half* pw = sP + (size_t)(wid * 16) * 72;
        #pragma unroll
        for (int ntl = 0; ntl < 8; ntl++) {
            int c0 = ntl * 8 + t * 2;
            *(__half2*)&pw[g * 72 + c0]       = __floats2half2_rn(sacc[ntl][0], sacc[ntl][1]);
            *(__half2*)&pw[(g + 8) * 72 + c0] = __floats2half2_rn(sacc[ntl][2], sacc[ntl][3]);
        }
        __syncwarp();
        #pragma unroll
        for (int s = 0; s < 4; s++) {
            uint32_t pf[4];
            ldsm4(pf, sPb + a_base + s * 32);
            uint32_t bfr[8][2];
            #pragma unroll
            for (int p = 0; p < 4; p++) {
                uint32_t rr[4];
                ldsm4t(rr, sVb + bV_base + s * (16 * 144) + p * 32);
                bfr[2 * p][0]     = rr[0]; bfr[2 * p][1]     = rr[1];
                bfr[2 * p + 1][0] = rr[2]; bfr[2 * p + 1][1] = rr[3];
            }
            #pragma unroll
            for (int ntl = 0; ntl < 8; ntl++)
                mma_f16(o[ntl], pf, bfr[ntl]);
        }
    }

    float rl0 = 1.f / l_run[0], rl1 = 1.f / l_run[1];
    int r0 = wid * 16 + g;
    #pragma unroll
    for (int ntl = 0; ntl < 8; ntl++) {
        int col = ntl * 8 + t * 2;
        *(__half2*)&cp[(size_t)r0 * H_ + col] =
            __floats2half2_rn(o[ntl][0] * rl0, o[ntl][1] * rl0);
        *(__half2*)&cp[(size_t)(r0 + 8) * H_ + col] =
            __floats2half2_rn(o[ntl][2] * rl1, o[ntl][3] * rl1);
    }
}

// ---------------- small SIMT GEMM (pooler + classifier only) ----------------
template<int ACT> // 0 none, 2 tanh
__global__ void gemm_kernel(const float* __restrict__ A, const float* __restrict__ Bm,
                            const float* __restrict__ bias, float* __restrict__ C,
                            int M, int N, int K, int lda, int ldb, int ldc)
{
    __shared__ float As[16][65];
    __shared__ float Bs[16][65];

    int m0 = blockIdx.y * 64;
    int n0 = blockIdx.x * 64;
    int tid = threadIdx.x;
    int tx = tid & 15, ty = tid >> 4;

    float acc[4][4] = {};

    for (int k0 = 0; k0 < K; k0 += 16) {
        #pragma unroll
        for (int i = tid; i < 64 * 16; i += 256) {
            int m = i >> 4, k = i & 15;
            int gm = m0 + m, gk = k0 + k;
            As[k][m] = (gm < M && gk < K) ? A[(long)gm * lda + gk] : 0.f;
        }
        #pragma unroll
        for (int i = tid; i < 16 * 64; i += 256) {
            int k = i >> 6, n = i & 63;
            int gk = k0 + k, gn = n0 + n;
            Bs[k][n] = (gk < K && gn < N) ? Bm[(long)gk * ldb + gn] : 0.f;
        }
        __syncthreads();
        #pragma unroll
        for (int k = 0; k < 16; k++) {
            float a[4], bb[4];
            #pragma unroll
            for (int i = 0; i < 4; i++) a[i] = As[k][ty * 4 + i];
            #pragma unroll
            for (int j = 0; j < 4; j++) bb[j] = Bs[k][tx * 4 + j];
            #pragma unroll
            for (int i = 0; i < 4; i++)
                #pragma unroll
                for (int j = 0; j < 4; j++)
                    acc[i][j] = fmaf(a[i], bb[j], acc[i][j]);
        }
        __syncthreads();
    }

    #pragma unroll
    for (int i = 0; i < 4; i++) {
        int gm = m0 + ty * 4 + i;
        if (gm >= M) continue;
        #pragma unroll
        for (int j = 0; j < 4; j++) {
            int gn = n0 + tx * 4 + j;
            if (gn >= N) continue;
            float v = acc[i][j];
            if (bias) v += bias[gn];
            if (ACT == 2) v = tanhf(v);
            C[(long)gm * ldc + gn] = v;
        }
    }
}

// ---------------- log-softmax + NLL loss + output write ----------------
__global__ void loss_kernel(const float* __restrict__ logits, const int* __restrict__ tgt,
                            float* __restrict__ out, int out_size)
{
    int lane = threadIdx.x;
    float lp = 0.f;
    if (lane < B_) {
        const float* row = logits + lane * LAB_;
        float mx = row[0];
        #pragma unroll
        for (int j = 1; j < LAB_; j++) mx = fmaxf(mx, row[j]);
        float s = 0.f;
        #pragma unroll
        for (int j = 0; j < LAB_; j++) s += expf(row[j] - mx);
        lp = row[tgt[lane]] - mx - logf(s);
    }
    #pragma unroll
    for (int o = 16; o; o >>= 1) lp += __shfl_down_sync(0xffffffffu, lp, o);
    int ofs = (out_size > B_ * LAB_) ? 1 : 0;
    if (lane == 0 && ofs) out[0] = -lp / (float)B_;
    for (int i = lane; i < B_ * LAB_; i += 32) out[ofs + i] = logits[i];
}

// ---------------- host launch ----------------
extern "C" void kernel_launch(void* const* d_in, const int* in_sizes, int n_in,
                              void* d_out, int out_size)
{
    const int*   src  = (const int*)d_in[0];
    const int*   seg  = (const int*)d_in[1];
    const int*   tgt  = (const int*)d_in[2];
    const int*   tib  = (const int*)d_in[3];
    const float* we   = (const float*)d_in[4];
    const float* pe   = (const float*)d_in[5];
    const float* se   = (const float*)d_in[6];
    const float* elng = (const float*)d_in[7];
    const float* elnb = (const float*)d_in[8];
    const float* Wq   = (const float*)d_in[9];
    const float* bq   = (const float*)d_in[10];
    const float* Wk   = (const float*)d_in[11];
    const float* bk   = (const float*)d_in[12];
    const float* Wv   = (const float*)d_in[13];
    const float* bv   = (const float*)d_in[14];
    const float* Wo   = (const float*)d_in[15];
    const float* bo   = (const float*)d_in[16];
    const float* ln1g = (const float*)d_in[17];
    const float* ln1b = (const float*)d_in[18];
    const float* Wf1  = (const float*)d_in[19];
    const float* bf1  = (const float*)d_in[20];
    const float* Wf2  = (const float*)d_in[21];
    const float* bf2  = (const float*)d_in[22];
    const float* ln2g = (const float*)d_in[23];
    const float* ln2b = (const float*)d_in[24];
    const float* Wp1  = (const float*)d_in[25];
    const float* bp1  = (const float*)d_in[26];
    const float* Wp2  = (const float*)d_in[27];
    const float* bp2  = (const float*)d_in[28];
    const float* sel  = (const float*)d_in[29];
    (void)in_sizes; (void)n_in;

    float *x, *tmp, *hidden, *logits, *bqkv;
    __half *xh, *qkv, *ctxh, *ffh, *wqkvT, *woT, *wf1T, *wf2T;
    cudaGetSymbolAddress((void**)&x,     g_x);
    cudaGetSymbolAddress((void**)&xh,    g_xh);
    cudaGetSymbolAddress((void**)&qkv,   g_qkv);
    cudaGetSymbolAddress((void**)&ctxh,  g_ctxh);
    cudaGetSymbolAddress((void**)&tmp,   g_tmp);
    cudaGetSymbolAddress((void**)&ffh,   g_ffh);
    cudaGetSymbolAddress((void**)&hidden,g_hidden);
    cudaGetSymbolAddress((void**)&logits,g_logits);
    cudaGetSymbolAddress((void**)&wqkvT, g_wqkvT);
    cudaGetSymbolAddress((void**)&woT,   g_woT);
    cudaGetSymbolAddress((void**)&wf1T,  g_wf1T);
    cudaGetSymbolAddress((void**)&wf2T,  g_wf2T);
    cudaGetSymbolAddress((void**)&bqkv,  g_bqkv);

    cudaFuncSetAttribute(hgemm<0,1>, cudaFuncAttributeMaxDynamicSharedMemorySize, HG_SMEM);
    cudaFuncSetAttribute(hgemm<0,0>, cudaFuncAttributeMaxDynamicSharedMemorySize, HG_SMEM);
    cudaFuncSetAttribute(hgemm<1,1>, cudaFuncAttributeMaxDynamicSharedMemorySize, HG_SMEM);
    cudaFuncSetAttribute(attn_kernel, cudaFuncAttributeMaxDynamicSharedMemorySize, ATTN_SMEM);

    const int Mtok = B_ * S_;                    // 8192

    // weight prep
    {
        dim3 tb(32, 8);
        dim3 gHH(H_ / 32, H_ / 32, L_);
        transpose_cvt<<<gHH, tb>>>(Wq, wqkvT,                   H_, H_, (long)QKVN * H_);
        transpose_cvt<<<gHH, tb>>>(Wk, wqkvT + (size_t)H_*H_,   H_, H_, (long)QKVN * H_);
        transpose_cvt<<<gHH, tb>>>(Wv, wqkvT + (size_t)2*H_*H_, H_, H_, (long)QKVN * H_);
        transpose_cvt<<<gHH, tb>>>(Wo, woT, H_, H_, (long)H_ * H_);
        dim3 gF1(FF_ / 32, H_ / 32, L_);
        transpose_cvt<<<gF1, tb>>>(Wf1, wf1T, H_, FF_, (long)FF_ * H_);
        dim3 gF2(H_ / 32, FF_ / 32, L_);
        transpose_cvt<<<gF2, tb>>>(Wf2, wf2T, FF_, H_, (long)H_ * FF_);
        concat_bias<<<(L_ * QKVN + 255) / 256, 256>>>(bq, bk, bv, bqkv);
    }

    embed_kernel<<<Mtok, 256>>>(src, seg, tib, we, pe, se, elng, elnb, sel, x, xh);

    dim3 gQKV(QKVN / 128, Mtok / 128);   // (18, 64)
    dim3 gH  (H_   / 128, Mtok / 128);   // (6, 64)
    dim3 gFF (FF_  / 128, Mtok / 128);   // (24, 64)
    dim3 gAtt(S_ / 128, B_ * NH_);       // (4, 192)

    for (int l = 0; l < L_; l++) {
        const __half* wqkv = wqkvT + (size_t)l * QKVN * H_;
        const __half* wo   = woT   + (size_t)l * H_ * H_;
        const __half* wf1  = wf1T  + (size_t)l * H_ * FF_;
        const __half* wf2  = wf2T  + (size_t)l * FF_ * H_;

        hgemm<0,1><<<gQKV, 256, HG_SMEM>>>(xh, wqkv, bqkv + l * QKVN, qkv,
                                           H_, H_, H_, QKVN);
        attn_kernel<<<gAtt, 256, ATTN_SMEM>>>(qkv, seg, ctxh);
        hgemm<0,0><<<gH, 256, HG_SMEM>>>(ctxh, wo, bo + l * H_, tmp,
                                         H_, H_, H_, H_);
        add_ln_kernel<<<Mtok, 256>>>(x, tmp, ln1g + l * H_, ln1b + l * H_, xh);

        hgemm<1,1><<<gFF, 256, HG_SMEM>>>(xh, wf1, bf1 + l * FF_, ffh,
                                          H_, H_, H_, FF_);
        hgemm<0,0><<<gH, 256, HG_SMEM>>>(ffh, wf2, bf2 + l * H_, tmp,
                                         FF_, FF_, FF_, H_);
        add_ln_kernel<<<Mtok, 256>>>(x, tmp, ln2g + l * H_, ln2b + l * H_, xh);
    }

    dim3 gPool((H_ + 63) / 64, 1);
    gemm_kernel<2><<<gPool, 256>>>(x, Wp1, bp1, hidden, B_, H_, H_,
                                   S_ * H_, H_, H_);
    dim3 gCls(1, 1);
    gemm_kernel<0><<<gCls, 256>>>(hidden, Wp2, bp2, logits, B_, LAB_, H_,
                                  H_, LAB_, LAB_);

    loss_kernel<<<1, 32>>>(logits, tgt, (float*)d_out, out_size);
}

// round 8
// speedup vs baseline: 15.3696x; 1.1085x over previous
#include <cuda_runtime.h>
#include <cuda_fp16.h>
#include <math.h>
#include <stdint.h>

#define B_   16
#define S_   512
#define H_   768
#define NH_  12
#define L_   6
#define FF_  3072
#define DH_  64
#define LAB_ 10
#define QKVN 2304          // 3*H

// ---------------- scratch (device globals; no allocations allowed) ----------
__device__ float  g_x   [(size_t)B_*S_*H_];
__device__ __half g_xh  [(size_t)B_*S_*H_];
__device__ __half g_qkv [(size_t)B_*S_*QKVN];
__device__ __half g_ctxh[(size_t)B_*S_*H_];
__device__ float  g_tmp [(size_t)B_*S_*H_];
__device__ __half g_ffh [(size_t)B_*S_*FF_];
__device__ float  g_hidden[(size_t)B_*H_];
__device__ float  g_logits[(size_t)B_*LAB_];
// transposed + fp16 weights [N][K]
__device__ __half g_wqkvT[(size_t)L_*QKVN*H_];
__device__ __half g_woT  [(size_t)L_*H_*H_];
__device__ __half g_wf1T [(size_t)L_*FF_*H_];
__device__ __half g_wf2T [(size_t)L_*H_*FF_];
__device__ float  g_bqkv [(size_t)L_*QKVN];

// ---------------- small helpers ----------------
__device__ __forceinline__ uint32_t smem_u32(const void* p) {
    return (uint32_t)__cvta_generic_to_shared(p);
}

__device__ __forceinline__ void cp16s(uint32_t s, const void* g) {
    asm volatile("cp.async.ca.shared.global [%0], [%1], 16;\n" :: "r"(s), "l"(g));
}

__device__ __forceinline__ void ldsm4(uint32_t* r, uint32_t a) {
    asm volatile("ldmatrix.sync.aligned.m8n8.x4.shared.b16 {%0,%1,%2,%3}, [%4];"
                 : "=r"(r[0]), "=r"(r[1]), "=r"(r[2]), "=r"(r[3]) : "r"(a));
}

__device__ __forceinline__ void ldsm4t(uint32_t* r, uint32_t a) {
    asm volatile("ldmatrix.sync.aligned.m8n8.x4.trans.shared.b16 {%0,%1,%2,%3}, [%4];"
                 : "=r"(r[0]), "=r"(r[1]), "=r"(r[2]), "=r"(r[3]) : "r"(a));
}

__device__ __forceinline__ void mma_f16(float* c, const uint32_t* a, const uint32_t* b) {
    asm volatile(
        "mma.sync.aligned.m16n8k16.row.col.f32.f16.f16.f32 "
        "{%0,%1,%2,%3}, {%4,%5,%6,%7}, {%8,%9}, {%0,%1,%2,%3};\n"
        : "+f"(c[0]), "+f"(c[1]), "+f"(c[2]), "+f"(c[3])
        : "r"(a[0]), "r"(a[1]), "r"(a[2]), "r"(a[3]), "r"(b[0]), "r"(b[1]));
}

__device__ __forceinline__ float gelu_tanh(float v) {
    float c = v * v * v;
    return 0.5f * v * (1.f + tanhf(0.7978845608028654f * (v + 0.044715f * c)));
}

// ---------------- block reductions ----------------
__device__ __forceinline__ float block_reduce_sum(float v, float* sbuf) {
    __syncthreads();
    #pragma unroll
    for (int o = 16; o; o >>= 1) v += __shfl_down_sync(0xffffffffu, v, o);
    int lane = threadIdx.x & 31, w = threadIdx.x >> 5;
    if (lane == 0) sbuf[w] = v;
    __syncthreads();
    if (w == 0) {
        int nw = (blockDim.x + 31) >> 5;
        v = (lane < nw) ? sbuf[lane] : 0.f;
        #pragma unroll
        for (int o = 16; o; o >>= 1) v += __shfl_down_sync(0xffffffffu, v, o);
        if (lane == 0) sbuf[0] = v;
    }
    __syncthreads();
    return sbuf[0];
}

// ---------------- weight transpose + fp16 convert ----------------
__global__ void transpose_cvt(const float* __restrict__ in, __half* __restrict__ out,
                              int R, int C, long ozs)
{
    in  += (size_t)blockIdx.z * R * C;
    out += (size_t)blockIdx.z * ozs;
    __shared__ float t[32][33];
    int c0 = blockIdx.x * 32, r0 = blockIdx.y * 32;
    int tx = threadIdx.x, ty = threadIdx.y;
    #pragma unroll
    for (int i = 0; i < 32; i += 8)
        t[ty + i][tx] = in[(size_t)(r0 + ty + i) * C + c0 + tx];
    __syncthreads();
    #pragma unroll
    for (int i = 0; i < 32; i += 8)
        out[(size_t)(c0 + ty + i) * R + r0 + tx] = __float2half_rn(t[tx][ty + i]);
}

__global__ void concat_bias(const float* __restrict__ bq, const float* __restrict__ bk,
                            const float* __restrict__ bv, float* __restrict__ out)
{
    int i = blockIdx.x * 256 + threadIdx.x;
    if (i >= L_ * QKVN) return;
    int l = i / QKVN, r = i - l * QKVN;
    float val;
    if (r < H_)            val = bq[l * H_ + r];
    else if (r < 2 * H_)   val = bk[l * H_ + r - H_];
    else                   val = bv[l * H_ + r - 2 * H_];
    out[i] = val;
}

// ---------------- embedding + LN + selection ----------------
__global__ void embed_kernel(const int* __restrict__ src, const int* __restrict__ seg,
                             const int* __restrict__ tib,
                             const float* __restrict__ we, const float* __restrict__ pe,
                             const float* __restrict__ se,
                             const float* __restrict__ g, const float* __restrict__ bta,
                             const float* __restrict__ sel, float* __restrict__ x,
                             __half* __restrict__ xh)
{
    int t = blockIdx.x;
    int s = t % S_;
    __shared__ float e[H_];
    __shared__ float sbuf[32];
    int w = src[t], sg = seg[t];
    const float* wr = we + (size_t)w * H_;
    const float* pr = pe + (size_t)s * H_;
    const float* sr = se + (size_t)sg * H_;
    float lsum = 0.f, lsq = 0.f;
    for (int j = threadIdx.x; j < H_; j += blockDim.x) {
        float val = wr[j] + pr[j] + sr[j];
        e[j] = val; lsum += val; lsq += val * val;
    }
    float tot = block_reduce_sum(lsum, sbuf);
    float totsq = block_reduce_sum(lsq, sbuf);
    float mean = tot / H_;
    float var  = totsq / H_ - mean * mean;
    float inv  = rsqrtf(var + 1e-5f);
    float f = sel[tib[t]];
    float* xo = x + (size_t)t * H_;
    __half* xho = xh + (size_t)t * H_;
    for (int j = threadIdx.x; j < H_; j += blockDim.x) {
        float val = ((e[j] - mean) * inv * g[j] + bta[j]) * f;
        xo[j] = val;
        xho[j] = __float2half_rn(val);
    }
}

// ---------------- residual add + LN (in place on x, writes half copy) -------
__global__ void add_ln_kernel(float* __restrict__ x, const float* __restrict__ t,
                              const float* __restrict__ g, const float* __restrict__ bta,
                              __half* __restrict__ xh)
{
    int row = blockIdx.x;
    __shared__ float e[H_];
    __shared__ float sbuf[32];
    float* xr = x + (size_t)row * H_;
    __half* xhr = xh + (size_t)row * H_;
    const float* tr = t + (size_t)row * H_;
    float lsum = 0.f, lsq = 0.f;
    for (int j = threadIdx.x; j < H_; j += blockDim.x) {
        float val = xr[j] + tr[j];
        e[j] = val; lsum += val; lsq += val * val;
    }
    float tot = block_reduce_sum(lsum, sbuf);
    float totsq = block_reduce_sum(lsq, sbuf);
    float mean = tot / H_;
    float var  = totsq / H_ - mean * mean;
    float inv  = rsqrtf(var + 1e-5f);
    for (int j = threadIdx.x; j < H_; j += blockDim.x) {
        float val = (e[j] - mean) * inv * g[j] + bta[j];
        xr[j] = val;
        xhr[j] = __float2half_rn(val);
    }
}

// =====================================================================
// FP16 tensor-core GEMM: out = act(A[M,K] @ Bw[N,K]^T + bias)
// BM=128, BN=128, BK=64 halves. 256 threads = 8 warps (wm 0..3, wn 0..1),
// warp tile 32x64, m16n8k16 mma, 3-stage cp.async, XOR-swizzled smem
// (128B rows, chunk ^= row&7), ONE __syncthreads per k-tile.
// ACT: 0 none, 1 gelu. OUTH: 1 -> write __half, 0 -> write float.
// =====================================================================
#define HG_SMEM 98304   // 3 stages * (16KB A + 16KB B)

template<int ACT, int OUTH>
__global__ void __launch_bounds__(256)
hgemm(const __half* __restrict__ A, const __half* __restrict__ Bw,
      const float* __restrict__ bias, void* __restrict__ Cout,
      int K, int lda, int ldb, int ldc)
{
    extern __shared__ char smem[];
    const uint32_t sb = smem_u32(smem);

    const int m0  = blockIdx.y * 128;
    const int n0  = blockIdx.x * 128;
    const int tid = threadIdx.x;
    const int lane = tid & 31, wid = tid >> 5;
    const int wm = wid & 3, wn = wid >> 2;
    const int g = lane >> 2, t = lane & 3;

    const int nt = K >> 6;     // BK = 64 halves = 128B rows

    auto load_st = [&](int kt) {
        int st = kt % 3;
        int k0 = kt << 6;
        uint32_t ab = sb + st * 32768;
        uint32_t bb = ab + 16384;
        #pragma unroll
        for (int i = 0; i < 4; i++) {
            int c = i * 256 + tid;              // 1024 chunks per operand
            int row = c >> 3, ch = c & 7;
            uint32_t d = ((uint32_t)row << 7) + (uint32_t)((ch ^ (row & 7)) << 4);
            cp16s(ab + d, A  + (size_t)(m0 + row) * lda + k0 + ch * 8);
            cp16s(bb + d, Bw + (size_t)(n0 + row) * ldb + k0 + ch * 8);
        }
        asm volatile("cp.async.commit_group;" ::: "memory");
    };

    float acc[2][8][4];
    #pragma unroll
    for (int i = 0; i < 2; i++)
        #pragma unroll
        for (int j = 0; j < 8; j++)
            #pragma unroll
            for (int r = 0; r < 4; r++) acc[i][j][r] = 0.f;

    load_st(0);
    if (nt > 1) load_st(1);

    // precomputed ldsm row/chunk components
    const int arow_b = wm * 32 + (lane & 15);                       // + mt*16
    const int achk_b = (lane >> 4);                                 // + ks*2
    const int brow_b = wn * 64 + ((lane >> 4) << 3) + (lane & 7);   // + p*16
    const int bchk_b = ((lane >> 3) & 1);                           // + ks*2

    for (int kt = 0; kt < nt; kt++) {
        int st = kt % 3;
        if (kt + 1 < nt)
            asm volatile("cp.async.wait_group 1;" ::: "memory");
        else
            asm volatile("cp.async.wait_group 0;" ::: "memory");
        __syncthreads();
        if (kt + 2 < nt) load_st(kt + 2);

        uint32_t ab = sb + st * 32768;
        uint32_t bb = ab + 16384;

        #pragma unroll
        for (int ks = 0; ks < 4; ks++) {
            uint32_t afr[2][4];
            #pragma unroll
            for (int mt = 0; mt < 2; mt++) {
                int row = arow_b + mt * 16;
                int ch  = achk_b + ks * 2;
                ldsm4(afr[mt], ab + ((uint32_t)row << 7)
                                  + (uint32_t)((ch ^ (row & 7)) << 4));
            }
            uint32_t bfr[8][2];
            #pragma unroll
            for (int p = 0; p < 4; p++) {
                int row = brow_b + p * 16;
                int ch  = bchk_b + ks * 2;
                uint32_t rr[4];
                ldsm4(rr, bb + ((uint32_t)row << 7)
                             + (uint32_t)((ch ^ (row & 7)) << 4));
                bfr[2 * p][0]     = rr[0]; bfr[2 * p][1]     = rr[1];
                bfr[2 * p + 1][0] = rr[2]; bfr[2 * p + 1][1] = rr[3];
            }
            #pragma unroll
            for (int mt = 0; mt < 2; mt++)
                #pragma unroll
                for (int ntl = 0; ntl < 8; ntl++)
                    mma_f16(acc[mt][ntl], afr[mt], bfr[ntl]);
        }
        // no trailing barrier: next iteration's barrier (after its wait_group)
        // protects buffer reuse.
    }

    #pragma unroll
    for (int mt = 0; mt < 2; mt++) {
        #pragma unroll
        for (int ntl = 0; ntl < 8; ntl++) {
            int row = m0 + wm * 32 + mt * 16 + g;
            int col = n0 + wn * 64 + ntl * 8 + t * 2;
            float bv0 = bias[col], bv1 = bias[col + 1];
            #pragma unroll
            for (int half_ = 0; half_ < 2; half_++) {
                int r = row + half_ * 8;
                float v0 = acc[mt][ntl][half_ * 2 + 0] + bv0;
                float v1 = acc[mt][ntl][half_ * 2 + 1] + bv1;
                if (ACT == 1) { v0 = gelu_tanh(v0); v1 = gelu_tanh(v1); }
                if (OUTH) {
                    __half2* C = (__half2*)((__half*)Cout + (size_t)r * ldc + col);
                    *C = __floats2half2_rn(v0, v1);
                } else {
                    float* C = (float*)Cout + (size_t)r * ldc + col;
                    *(float2*)C = make_float2(v0, v1);
                }
            }
        }
    }
}

// =====================================================================
// Fused flash-attention, fp16 operands / fp32 softmax+accum (as R6).
// =====================================================================
#define ATTN_SMEM  ((128*72 + 2*64*72 + 2*64*72) * 2 + 512 * 4)   // 57344

__global__ void __launch_bounds__(256)
attn_kernel(const __half* __restrict__ qkv, const int* __restrict__ seg,
            __half* __restrict__ ctx)
{
    extern __shared__ __half hsm[];
    __half* sP    = hsm;                       // 128*72 (Q staging, then P)
    __half* sK    = sP + 128 * 72;             // 2 * 64*72
    __half* sV    = sK + 2 * 64 * 72;          // 2 * 64*72
    float*  smask = (float*)(sV + 2 * 64 * 72);

    const int bh = blockIdx.y;
    const int b = bh / NH_, h = bh - b * NH_;
    const int q0 = blockIdx.x * 128;

    const __half* qp = qkv + (size_t)b * S_ * QKVN + h * DH_;
    const __half* kp = qp + H_;
    __half* cp = ctx + ((size_t)b * S_ + q0) * H_ + h * DH_;

    const int tid = threadIdx.x, lane = tid & 31, wid = tid >> 5;
    const int g = lane >> 2, t = lane & 3;
    const uint32_t sPb = smem_u32(sP);
    const uint32_t sKb0 = smem_u32(sK);
    const uint32_t sVb0 = smem_u32(sV);

    for (int i = tid; i < S_; i += 256)
        smask[i] = (seg[b * S_ + i] > 0) ? 0.f : -1e9f;

    #pragma unroll
    for (int i = 0; i < 4; i++) {
        int c = i * 256 + tid;
        int row = c >> 3, kc = (c & 7) << 3;
        cp16s(sPb + (uint32_t)row * 144 + ((c & 7) << 4),
              qp + (size_t)(q0 + row) * QKVN + kc);
    }
    asm volatile("cp.async.commit_group;" ::: "memory");
    asm volatile("cp.async.wait_group 0;" ::: "memory");
    __syncthreads();

    const uint32_t a_base = (uint32_t)(wid * 16 + (lane & 15)) * 144 + ((lane >> 4) << 4);
    uint32_t qf[4][4];
    #pragma unroll
    for (int s = 0; s < 4; s++)
        ldsm4(qf[s], sPb + a_base + s * 32);
    __syncthreads();

    auto load_kv = [&](int kt, int buf) {
        int kbase = kt * 64;
        #pragma unroll
        for (int i = 0; i < 2; i++) {
            int c = i * 256 + tid;
            int row = c >> 3, kc = (c & 7) << 3;
            const __half* kg = kp + (size_t)(kbase + row) * QKVN + kc;
            uint32_t d = (uint32_t)row * 144 + ((c & 7) << 4);
            cp16s(sKb0 + buf * 9216 + d, kg);
            cp16s(sVb0 + buf * 9216 + d, kg + H_);
        }
        asm volatile("cp.async.commit_group;" ::: "memory");
    };
    load_kv(0, 0);

    const uint32_t bK_base = (uint32_t)(((lane >> 4) << 3) + (lane & 7)) * 144
                           + (((lane >> 3) & 1) << 4);
    const uint32_t bV_base = (uint32_t)(lane & 15) * 144 + (((lane >> 4) & 1) << 4);

    float m_run[2] = {-1e30f, -1e30f};
    float l_run[2] = {0.f, 0.f};
    float o[8][4];
    #pragma unroll
    for (int ntl = 0; ntl < 8; ntl++)
        #pragma unroll
        for (int r = 0; r < 4; r++) o[ntl][r] = 0.f;

    for (int kt = 0; kt < S_ / 64; kt++) {
        int buf = kt & 1;
        asm volatile("cp.async.wait_group 0;" ::: "memory");
        __syncthreads();
        if (kt + 1 < S_ / 64) load_kv(kt + 1, buf ^ 1);

        uint32_t sKb = sKb0 + buf * 9216;
        uint32_t sVb = sVb0 + buf * 9216;

        float sacc[8][4];
        #pragma unroll
        for (int ntl = 0; ntl < 8; ntl++)
            #pragma unroll
            for (int r = 0; r < 4; r++) sacc[ntl][r] = 0.f;
        #pragma unroll
        for (int s = 0; s < 4; s++) {
            uint32_t bfr[8][2];
            #pragma unroll
            for (int p = 0; p < 4; p++) {
                uint32_t rr[4];
                ldsm4(rr, sKb + bK_base + p * (16 * 144) + s * 32);
                bfr[2 * p][0]     = rr[0]; bfr[2 * p][1]     = rr[1];
                bfr[2 * p + 1][0] = rr[2]; bfr[2 * p + 1][1] = rr[3];
            }
            #pragma unroll
            for (int ntl = 0; ntl < 8; ntl++)
                mma_f16(sacc[ntl], qf[s], bfr[ntl]);
        }

        float tmax0 = -1e30f, tmax1 = -1e30f;
        #pragma unroll
        for (int ntl = 0; ntl < 8; ntl++) {
            int col = kt * 64 + ntl * 8 + t * 2;
            float mb0 = smask[col], mb1 = smask[col + 1];
            sacc[ntl][0] = fmaf(sacc[ntl][0], 0.125f, mb0);
            sacc[ntl][1] = fmaf(sacc[ntl][1], 0.125f, mb1);
            sacc[ntl][2] = fmaf(sacc[ntl][2], 0.125f, mb0);
            sacc[ntl][3] = fmaf(sacc[ntl][3], 0.125f, mb1);
            tmax0 = fmaxf(tmax0, fmaxf(sacc[ntl][0], sacc[ntl][1]));
            tmax1 = fmaxf(tmax1, fmaxf(sacc[ntl][2], sacc[ntl][3]));
        }
        tmax0 = fmaxf(tmax0, __shfl_xor_sync(0xffffffffu, tmax0, 1));
        tmax0 = fmaxf(tmax0, __shfl_xor_sync(0xffffffffu, tmax0, 2));
        tmax1 = fmaxf(tmax1, __shfl_xor_sync(0xffffffffu, tmax1, 1));
        tmax1 = fmaxf(tmax1, __shfl_xor_sync(0xffffffffu, tmax1, 2));
        float mnew0 = fmaxf(m_run[0], tmax0);
        float mnew1 = fmaxf(m_run[1], tmax1);
        float al0 = __expf(m_run[0] - mnew0);
        float al1 = __expf(m_run[1] - mnew1);
        float ts0 = 0.f, ts1 = 0.f;
        #pragma unroll
        for (int ntl = 0; ntl < 8; ntl++) {
            sacc[ntl][0] = __expf(sacc[ntl][0] - mnew0);
            sacc[ntl][1] = __expf(sacc[ntl][1] - mnew0);
            sacc[ntl][2] = __expf(sacc[ntl][2] - mnew1);
            sacc[ntl][3] = __expf(sacc[ntl][3] - mnew1);
            ts0 += sacc[ntl][0] + sacc[ntl][1];
            ts1 += sacc[ntl][2] + sacc[ntl][3];
        }
        ts0 += __shfl_xor_sync(0xffffffffu, ts0, 1);
        ts0 += __shfl_xor_sync(0xffffffffu, ts0, 2);
        ts1 += __shfl_xor_sync(0xffffffffu, ts1, 1);
        ts1 += __shfl_xor_sync(0xffffffffu, ts1, 2);
        l_run[0] = l_run[0] * al0 + ts0;
        l_run[1] = l_run[1] * al1 + ts1;
        m_run[0] = mnew0; m_run[1] = mnew1;
        #pragma unroll
        for (int ntl = 0; ntl < 8; ntl++) {
            o[ntl][0] *= al0; o[ntl][1] *= al0;
            o[ntl][2] *= al1; o[ntl][3] *= al1;
        }

        __half* pw = sP + (size_t)(wid * 16) * 72;
        #pragma unroll
        for (int ntl = 0; ntl < 8; ntl++) {
            int c0 = ntl * 8 + t * 2;
            *(__half2*)&pw[g * 72 + c0]       = __floats2half2_rn(sacc[ntl][0], sacc[ntl][1]);
            *(__half2*)&pw[(g + 8) * 72 + c0] = __floats2half2_rn(sacc[ntl][2], sacc[ntl][3]);
        }
        __syncwarp();
        #pragma unroll
        for (int s = 0; s < 4; s++) {
            uint32_t pf[4];
            ldsm4(pf, sPb + a_base + s * 32);
            uint32_t bfr[8][2];
            #pragma unroll
            for (int p = 0; p < 4; p++) {
                uint32_t rr[4];
                ldsm4t(rr, sVb + bV_base + s * (16 * 144) + p * 32);
                bfr[2 * p][0]     = rr[0]; bfr[2 * p][1]     = rr[1];
                bfr[2 * p + 1][0] = rr[2]; bfr[2 * p + 1][1] = rr[3];
            }
            #pragma unroll
            for (int ntl = 0; ntl < 8; ntl++)
                mma_f16(o[ntl], pf, bfr[ntl]);
        }
    }

    float rl0 = 1.f / l_run[0], rl1 = 1.f / l_run[1];
    int r0 = wid * 16 + g;
    #pragma unroll
    for (int ntl = 0; ntl < 8; ntl++) {
        int col = ntl * 8 + t * 2;
        *(__half2*)&cp[(size_t)r0 * H_ + col] =
            __floats2half2_rn(o[ntl][0] * rl0, o[ntl][1] * rl0);
        *(__half2*)&cp[(size_t)(r0 + 8) * H_ + col] =
            __floats2half2_rn(o[ntl][2] * rl1, o[ntl][3] * rl1);
    }
}

// ---------------- small SIMT GEMM (pooler + classifier only) ----------------
template<int ACT> // 0 none, 2 tanh
__global__ void gemm_kernel(const float* __restrict__ A, const float* __restrict__ Bm,
                            const float* __restrict__ bias, float* __restrict__ C,
                            int M, int N, int K, int lda, int ldb, int ldc)
{
    __shared__ float As[16][65];
    __shared__ float Bs[16][65];

    int m0 = blockIdx.y * 64;
    int n0 = blockIdx.x * 64;
    int tid = threadIdx.x;
    int tx = tid & 15, ty = tid >> 4;

    float acc[4][4] = {};

    for (int k0 = 0; k0 < K; k0 += 16) {
        #pragma unroll
        for (int i = tid; i < 64 * 16; i += 256) {
            int m = i >> 4, k = i & 15;
            int gm = m0 + m, gk = k0 + k;
            As[k][m] = (gm < M && gk < K) ? A[(long)gm * lda + gk] : 0.f;
        }
        #pragma unroll
        for (int i = tid; i < 16 * 64; i += 256) {
            int k = i >> 6, n = i & 63;
            int gk = k0 + k, gn = n0 + n;
            Bs[k][n] = (gk < K && gn < N) ? Bm[(long)gk * ldb + gn] : 0.f;
        }
        __syncthreads();
        #pragma unroll
        for (int k = 0; k < 16; k++) {
            float a[4], bb[4];
            #pragma unroll
            for (int i = 0; i < 4; i++) a[i] = As[k][ty * 4 + i];
            #pragma unroll
            for (int j = 0; j < 4; j++) bb[j] = Bs[k][tx * 4 + j];
            #pragma unroll
            for (int i = 0; i < 4; i++)
                #pragma unroll
                for (int j = 0; j < 4; j++)
                    acc[i][j] = fmaf(a[i], bb[j], acc[i][j]);
        }
        __syncthreads();
    }

    #pragma unroll
    for (int i = 0; i < 4; i++) {
        int gm = m0 + ty * 4 + i;
        if (gm >= M) continue;
        #pragma unroll
        for (int j = 0; j < 4; j++) {
            int gn = n0 + tx * 4 + j;
            if (gn >= N) continue;
            float v = acc[i][j];
            if (bias) v += bias[gn];
            if (ACT == 2) v = tanhf(v);
            C[(long)gm * ldc + gn] = v;
        }
    }
}

// ---------------- log-softmax + NLL loss + output write ----------------
__global__ void loss_kernel(const float* __restrict__ logits, const int* __restrict__ tgt,
                            float* __restrict__ out, int out_size)
{
    int lane = threadIdx.x;
    float lp = 0.f;
    if (lane < B_) {
        const float* row = logits + lane * LAB_;
        float mx = row[0];
        #pragma unroll
        for (int j = 1; j < LAB_; j++) mx = fmaxf(mx, row[j]);
        float s = 0.f;
        #pragma unroll
        for (int j = 0; j < LAB_; j++) s += expf(row[j] - mx);
        lp = row[tgt[lane]] - mx - logf(s);
    }
    #pragma unroll
    for (int o = 16; o; o >>= 1) lp += __shfl_down_sync(0xffffffffu, lp, o);
    int ofs = (out_size > B_ * LAB_) ? 1 : 0;
    if (lane == 0 && ofs) out[0] = -lp / (float)B_;
    for (int i = lane; i < B_ * LAB_; i += 32) out[ofs + i] = logits[i];
}

// ---------------- host launch ----------------
extern "C" void kernel_launch(void* const* d_in, const int* in_sizes, int n_in,
                              void* d_out, int out_size)
{
    const int*   src  = (const int*)d_in[0];
    const int*   seg  = (const int*)d_in[1];
    const int*   tgt  = (const int*)d_in[2];
    const int*   tib  = (const int*)d_in[3];
    const float* we   = (const float*)d_in[4];
    const float* pe   = (const float*)d_in[5];
    const float* se   = (const float*)d_in[6];
    const float* elng = (const float*)d_in[7];
    const float* elnb = (const float*)d_in[8];
    const float* Wq   = (const float*)d_in[9];
    const float* bq   = (const float*)d_in[10];
    const float* Wk   = (const float*)d_in[11];
    const float* bk   = (const float*)d_in[12];
    const float* Wv   = (const float*)d_in[13];
    const float* bv   = (const float*)d_in[14];
    const float* Wo   = (const float*)d_in[15];
    const float* bo   = (const float*)d_in[16];
    const float* ln1g = (const float*)d_in[17];
    const float* ln1b = (const float*)d_in[18];
    const float* Wf1  = (const float*)d_in[19];
    const float* bf1  = (const float*)d_in[20];
    const float* Wf2  = (const float*)d_in[21];
    const float* bf2  = (const float*)d_in[22];
    const float* ln2g = (const float*)d_in[23];
    const float* ln2b = (const float*)d_in[24];
    const float* Wp1  = (const float*)d_in[25];
    const float* bp1  = (const float*)d_in[26];
    const float* Wp2  = (const float*)d_in[27];
    const float* bp2  = (const float*)d_in[28];
    const float* sel  = (const float*)d_in[29];
    (void)in_sizes; (void)n_in;

    float *x, *tmp, *hidden, *logits, *bqkv;
    __half *xh, *qkv, *ctxh, *ffh, *wqkvT, *woT, *wf1T, *wf2T;
    cudaGetSymbolAddress((void**)&x,     g_x);
    cudaGetSymbolAddress((void**)&xh,    g_xh);
    cudaGetSymbolAddress((void**)&qkv,   g_qkv);
    cudaGetSymbolAddress((void**)&ctxh,  g_ctxh);
    cudaGetSymbolAddress((void**)&tmp,   g_tmp);
    cudaGetSymbolAddress((void**)&ffh,   g_ffh);
    cudaGetSymbolAddress((void**)&hidden,g_hidden);
    cudaGetSymbolAddress((void**)&logits,g_logits);
    cudaGetSymbolAddress((void**)&wqkvT, g_wqkvT);
    cudaGetSymbolAddress((void**)&woT,   g_woT);
    cudaGetSymbolAddress((void**)&wf1T,  g_wf1T);
    cudaGetSymbolAddress((void**)&wf2T,  g_wf2T);
    cudaGetSymbolAddress((void**)&bqkv,  g_bqkv);

    cudaFuncSetAttribute(hgemm<0,1>, cudaFuncAttributeMaxDynamicSharedMemorySize, HG_SMEM);
    cudaFuncSetAttribute(hgemm<0,0>, cudaFuncAttributeMaxDynamicSharedMemorySize, HG_SMEM);
    cudaFuncSetAttribute(hgemm<1,1>, cudaFuncAttributeMaxDynamicSharedMemorySize, HG_SMEM);
    cudaFuncSetAttribute(attn_kernel, cudaFuncAttributeMaxDynamicSharedMemorySize, ATTN_SMEM);

    const int Mtok = B_ * S_;                    // 8192

    // weight prep
    {
        dim3 tb(32, 8);
        dim3 gHH(H_ / 32, H_ / 32, L_);
        transpose_cvt<<<gHH, tb>>>(Wq, wqkvT,                   H_, H_, (long)QKVN * H_);
        transpose_cvt<<<gHH, tb>>>(Wk, wqkvT + (size_t)H_*H_,   H_, H_, (long)QKVN * H_);
        transpose_cvt<<<gHH, tb>>>(Wv, wqkvT + (size_t)2*H_*H_, H_, H_, (long)QKVN * H_);
        transpose_cvt<<<gHH, tb>>>(Wo, woT, H_, H_, (long)H_ * H_);
        dim3 gF1(FF_ / 32, H_ / 32, L_);
        transpose_cvt<<<gF1, tb>>>(Wf1, wf1T, H_, FF_, (long)FF_ * H_);
        dim3 gF2(H_ / 32, FF_ / 32, L_);
        transpose_cvt<<<gF2, tb>>>(Wf2, wf2T, FF_, H_, (long)H_ * FF_);
        concat_bias<<<(L_ * QKVN + 255) / 256, 256>>>(bq, bk, bv, bqkv);
    }

    embed_kernel<<<Mtok, 256>>>(src, seg, tib, we, pe, se, elng, elnb, sel, x, xh);

    dim3 gQKV(QKVN / 128, Mtok / 128);   // (18, 64)
    dim3 gH  (H_   / 128, Mtok / 128);   // (6, 64)
    dim3 gFF (FF_  / 128, Mtok / 128);   // (24, 64)
    dim3 gAtt(S_ / 128, B_ * NH_);       // (4, 192)

    for (int l = 0; l < L_; l++) {
        const __half* wqkv = wqkvT + (size_t)l * QKVN * H_;
        const __half* wo   = woT   + (size_t)l * H_ * H_;
        const __half* wf1  = wf1T  + (size_t)l * H_ * FF_;
        const __half* wf2  = wf2T  + (size_t)l * FF_ * H_;

        hgemm<0,1><<<gQKV, 256, HG_SMEM>>>(xh, wqkv, bqkv + l * QKVN, qkv,
                                           H_, H_, H_, QKVN);
        attn_kernel<<<gAtt, 256, ATTN_SMEM>>>(qkv, seg, ctxh);
        hgemm<0,0><<<gH, 256, HG_SMEM>>>(ctxh, wo, bo + l * H_, tmp,
                                         H_, H_, H_, H_);
        add_ln_kernel<<<Mtok, 256>>>(x, tmp, ln1g + l * H_, ln1b + l * H_, xh);

        hgemm<1,1><<<gFF, 256, HG_SMEM>>>(xh, wf1, bf1 + l * FF_, ffh,
                                          H_, H_, H_, FF_);
        hgemm<0,0><<<gH, 256, HG_SMEM>>>(ffh, wf2, bf2 + l * H_, tmp,
                                         FF_, FF_, FF_, H_);
        add_ln_kernel<<<Mtok, 256>>>(x, tmp, ln2g + l * H_, ln2b + l * H_, xh);
    }

    dim3 gPool((H_ + 63) / 64, 1);
    gemm_kernel<2><<<gPool, 256>>>(x, Wp1, bp1, hidden, B_, H_, H_,
                                   S_ * H_, H_, H_);
    dim3 gCls(1, 1);
    gemm_kernel<0><<<gCls, 256>>>(hidden, Wp2, bp2, logits, B_, LAB_, H_,
                                  H_, LAB_, LAB_);

    loss_kernel<<<1, 32>>>(logits, tgt, (float*)d_out, out_size);
}

// round 9
// speedup vs baseline: 16.3110x; 1.0613x over previous
#include <cuda_runtime.h>
#include <cuda_fp16.h>
#include <math.h>
#include <stdint.h>

#define B_   16
#define S_   512
#define H_   768
#define NH_  12
#define L_   6
#define FF_  3072
#define DH_  64
#define LAB_ 10
#define QKVN 2304          // 3*H

// ---------------- scratch (device globals; no allocations allowed) ----------
__device__ float  g_x   [(size_t)B_*S_*H_];
__device__ __half g_xh  [(size_t)B_*S_*H_];
__device__ __half g_qkv [(size_t)B_*S_*QKVN];
__device__ __half g_ctxh[(size_t)B_*S_*H_];
__device__ float  g_tmp [(size_t)B_*S_*H_];
__device__ __half g_ffh [(size_t)B_*S_*FF_];
__device__ float  g_hidden[(size_t)B_*H_];
__device__ float  g_logits[(size_t)B_*LAB_];
// transposed + fp16 weights [N][K]
__device__ __half g_wqkvT[(size_t)L_*QKVN*H_];
__device__ __half g_woT  [(size_t)L_*H_*H_];
__device__ __half g_wf1T [(size_t)L_*FF_*H_];
__device__ __half g_wf2T [(size_t)L_*H_*FF_];
__device__ float  g_bqkv [(size_t)L_*QKVN];

// ---------------- small helpers ----------------
__device__ __forceinline__ uint32_t smem_u32(const void* p) {
    return (uint32_t)__cvta_generic_to_shared(p);
}

__device__ __forceinline__ void cp16s(uint32_t s, const void* g) {
    asm volatile("cp.async.ca.shared.global [%0], [%1], 16;\n" :: "r"(s), "l"(g));
}

__device__ __forceinline__ void ldsm4(uint32_t* r, uint32_t a) {
    asm volatile("ldmatrix.sync.aligned.m8n8.x4.shared.b16 {%0,%1,%2,%3}, [%4];"
                 : "=r"(r[0]), "=r"(r[1]), "=r"(r[2]), "=r"(r[3]) : "r"(a));
}

__device__ __forceinline__ void ldsm4t(uint32_t* r, uint32_t a) {
    asm volatile("ldmatrix.sync.aligned.m8n8.x4.trans.shared.b16 {%0,%1,%2,%3}, [%4];"
                 : "=r"(r[0]), "=r"(r[1]), "=r"(r[2]), "=r"(r[3]) : "r"(a));
}

__device__ __forceinline__ void mma_f16(float* c, const uint32_t* a, const uint32_t* b) {
    asm volatile(
        "mma.sync.aligned.m16n8k16.row.col.f32.f16.f16.f32 "
        "{%0,%1,%2,%3}, {%4,%5,%6,%7}, {%8,%9}, {%0,%1,%2,%3};\n"
        : "+f"(c[0]), "+f"(c[1]), "+f"(c[2]), "+f"(c[3])
        : "r"(a[0]), "r"(a[1]), "r"(a[2]), "r"(a[3]), "r"(b[0]), "r"(b[1]));
}

__device__ __forceinline__ float gelu_tanh(float v) {
    float c = v * v * v;
    return 0.5f * v * (1.f + tanhf(0.7978845608028654f * (v + 0.044715f * c)));
}

__device__ __forceinline__ float warp_sum(float v) {
    #pragma unroll
    for (int o = 16; o; o >>= 1) v += __shfl_xor_sync(0xffffffffu, v, o);
    return v;
}

// ---------------- weight transpose + fp16 convert ----------------
__global__ void transpose_cvt(const float* __restrict__ in, __half* __restrict__ out,
                              int R, int C, long ozs)
{
    in  += (size_t)blockIdx.z * R * C;
    out += (size_t)blockIdx.z * ozs;
    __shared__ float t[32][33];
    int c0 = blockIdx.x * 32, r0 = blockIdx.y * 32;
    int tx = threadIdx.x, ty = threadIdx.y;
    #pragma unroll
    for (int i = 0; i < 32; i += 8)
        t[ty + i][tx] = in[(size_t)(r0 + ty + i) * C + c0 + tx];
    __syncthreads();
    #pragma unroll
    for (int i = 0; i < 32; i += 8)
        out[(size_t)(c0 + ty + i) * R + r0 + tx] = __float2half_rn(t[tx][ty + i]);
}

__global__ void concat_bias(const float* __restrict__ bq, const float* __restrict__ bk,
                            const float* __restrict__ bv, float* __restrict__ out)
{
    int i = blockIdx.x * 256 + threadIdx.x;
    if (i >= L_ * QKVN) return;
    int l = i / QKVN, r = i - l * QKVN;
    float val;
    if (r < H_)            val = bq[l * H_ + r];
    else if (r < 2 * H_)   val = bk[l * H_ + r - H_];
    else                   val = bv[l * H_ + r - 2 * H_];
    out[i] = val;
}

// ---------------- embedding + LN + selection (warp per token) ----------------
__global__ void embed_kernel(const int* __restrict__ src, const int* __restrict__ seg,
                             const int* __restrict__ tib,
                             const float* __restrict__ we, const float* __restrict__ pe,
                             const float* __restrict__ se,
                             const float* __restrict__ g, const float* __restrict__ bta,
                             const float* __restrict__ sel, float* __restrict__ x,
                             __half* __restrict__ xh)
{
    int t = blockIdx.x * 8 + (threadIdx.x >> 5);
    int lane = threadIdx.x & 31;
    int s = t % S_;
    int w = src[t], sg = seg[t];
    const float4* wr = (const float4*)(we + (size_t)w * H_);
    const float4* pr = (const float4*)(pe + (size_t)s * H_);
    const float4* sr = (const float4*)(se + (size_t)sg * H_);
    float4 v[6];
    float lsum = 0.f, lsq = 0.f;
    #pragma unroll
    for (int i = 0; i < 6; i++) {
        int idx = lane + 32 * i;
        float4 a = wr[idx], bv4 = pr[idx], c = sr[idx];
        v[i].x = a.x + bv4.x + c.x; v[i].y = a.y + bv4.y + c.y;
        v[i].z = a.z + bv4.z + c.z; v[i].w = a.w + bv4.w + c.w;
        lsum += v[i].x + v[i].y + v[i].z + v[i].w;
        lsq  += v[i].x*v[i].x + v[i].y*v[i].y + v[i].z*v[i].z + v[i].w*v[i].w;
    }
    float tot = warp_sum(lsum), totsq = warp_sum(lsq);
    float mean = tot / H_;
    float var  = totsq / H_ - mean * mean;
    float inv  = rsqrtf(var + 1e-5f);
    float f = sel[tib[t]];
    float4* xo = (float4*)(x + (size_t)t * H_);
    uint2*  xho = (uint2*)(xh + (size_t)t * H_);
    const float4* g4 = (const float4*)g;
    const float4* b4 = (const float4*)bta;
    #pragma unroll
    for (int i = 0; i < 6; i++) {
        int idx = lane + 32 * i;
        float4 gg = g4[idx], bb = b4[idx], o;
        o.x = ((v[i].x - mean) * inv * gg.x + bb.x) * f;
        o.y = ((v[i].y - mean) * inv * gg.y + bb.y) * f;
        o.z = ((v[i].z - mean) * inv * gg.z + bb.z) * f;
        o.w = ((v[i].w - mean) * inv * gg.w + bb.w) * f;
        xo[idx] = o;
        __half2 h0 = __floats2half2_rn(o.x, o.y);
        __half2 h1 = __floats2half2_rn(o.z, o.w);
        uint2 u; u.x = *(uint32_t*)&h0; u.y = *(uint32_t*)&h1;
        xho[idx] = u;
    }
}

// ---------------- LN over tmp (residual already fused in GEMM) --------------
// warp per row: writes x (fp32) and xh (fp16)
__global__ void ln_kernel(const float* __restrict__ t,
                          const float* __restrict__ g, const float* __restrict__ bta,
                          float* __restrict__ x, __half* __restrict__ xh)
{
    int row = blockIdx.x * 8 + (threadIdx.x >> 5);
    int lane = threadIdx.x & 31;
    const float4* tr = (const float4*)(t + (size_t)row * H_);
    float4 v[6];
    float lsum = 0.f, lsq = 0.f;
    #pragma unroll
    for (int i = 0; i < 6; i++) {
        v[i] = tr[lane + 32 * i];
        lsum += v[i].x + v[i].y + v[i].z + v[i].w;
        lsq  += v[i].x*v[i].x + v[i].y*v[i].y + v[i].z*v[i].z + v[i].w*v[i].w;
    }
    float tot = warp_sum(lsum), totsq = warp_sum(lsq);
    float mean = tot / H_;
    float var  = totsq / H_ - mean * mean;
    float inv  = rsqrtf(var + 1e-5f);
    float4* xo = (float4*)(x + (size_t)row * H_);
    uint2*  xho = (uint2*)(xh + (size_t)row * H_);
    const float4* g4 = (const float4*)g;
    const float4* b4 = (const float4*)bta;
    #pragma unroll
    for (int i = 0; i < 6; i++) {
        int idx = lane + 32 * i;
        float4 gg = g4[idx], bb = b4[idx], o;
        o.x = (v[i].x - mean) * inv * gg.x + bb.x;
        o.y = (v[i].y - mean) * inv * gg.y + bb.y;
        o.z = (v[i].z - mean) * inv * gg.z + bb.z;
        o.w = (v[i].w - mean) * inv * gg.w + bb.w;
        xo[idx] = o;
        __half2 h0 = __floats2half2_rn(o.x, o.y);
        __half2 h1 = __floats2half2_rn(o.z, o.w);
        uint2 u; u.x = *(uint32_t*)&h0; u.y = *(uint32_t*)&h1;
        xho[idx] = u;
    }
}

// =====================================================================
// FP16 tensor-core GEMM: out = act(A[M,K] @ Bw[N,K]^T + bias [+ Res])
// BM=128, BN=128, BK=64 halves, 256 threads, warp tile 32x64,
// m16n8k16, 3-stage cp.async, XOR-swizzled 128B rows, 1 barrier/k-tile.
// ACT: 0 none, 1 gelu. OUTH: 1 half out, 0 float out. RES: add Res[row][col].
// =====================================================================
#define HG_SMEM 98304   // 3 stages * (16KB A + 16KB B)

template<int ACT, int OUTH, int RES>
__global__ void __launch_bounds__(256)
hgemm(const __half* __restrict__ A, const __half* __restrict__ Bw,
      const float* __restrict__ bias, void* __restrict__ Cout,
      const float* __restrict__ Res,
      int K, int lda, int ldb, int ldc)
{
    extern __shared__ char smem[];
    const uint32_t sb = smem_u32(smem);

    const int m0  = blockIdx.y * 128;
    const int n0  = blockIdx.x * 128;
    const int tid = threadIdx.x;
    const int lane = tid & 31, wid = tid >> 5;
    const int wm = wid & 3, wn = wid >> 2;
    const int g = lane >> 2, t = lane & 3;

    const int nt = K >> 6;     // BK = 64 halves = 128B rows

    auto load_st = [&](int kt) {
        int st = kt % 3;
        int k0 = kt << 6;
        uint32_t ab = sb + st * 32768;
        uint32_t bb = ab + 16384;
        #pragma unroll
        for (int i = 0; i < 4; i++) {
            int c = i * 256 + tid;              // 1024 chunks per operand
            int row = c >> 3, ch = c & 7;
            uint32_t d = ((uint32_t)row << 7) + (uint32_t)((ch ^ (row & 7)) << 4);
            cp16s(ab + d, A  + (size_t)(m0 + row) * lda + k0 + ch * 8);
            cp16s(bb + d, Bw + (size_t)(n0 + row) * ldb + k0 + ch * 8);
        }
        asm volatile("cp.async.commit_group;" ::: "memory");
    };

    float acc[2][8][4];
    #pragma unroll
    for (int i = 0; i < 2; i++)
        #pragma unroll
        for (int j = 0; j < 8; j++)
            #pragma unroll
            for (int r = 0; r < 4; r++) acc[i][j][r] = 0.f;

    load_st(0);
    if (nt > 1) load_st(1);

    const int arow_b = wm * 32 + (lane & 15);                       // + mt*16
    const int achk_b = (lane >> 4);                                 // + ks*2
    const int brow_b = wn * 64 + ((lane >> 4) << 3) + (lane & 7);   // + p*16
    const int bchk_b = ((lane >> 3) & 1);                           // + ks*2

    for (int kt = 0; kt < nt; kt++) {
        int st = kt % 3;
        if (kt + 1 < nt)
            asm volatile("cp.async.wait_group 1;" ::: "memory");
        else
            asm volatile("cp.async.wait_group 0;" ::: "memory");
        __syncthreads();
        if (kt + 2 < nt) load_st(kt + 2);

        uint32_t ab = sb + st * 32768;
        uint32_t bb = ab + 16384;

        #pragma unroll
        for (int ks = 0; ks < 4; ks++) {
            uint32_t afr[2][4];
            #pragma unroll
            for (int mt = 0; mt < 2; mt++) {
                int row = arow_b + mt * 16;
                int ch  = achk_b + ks * 2;
                ldsm4(afr[mt], ab + ((uint32_t)row << 7)
                                  + (uint32_t)((ch ^ (row & 7)) << 4));
            }
            uint32_t bfr[8][2];
            #pragma unroll
            for (int p = 0; p < 4; p++) {
                int row = brow_b + p * 16;
                int ch  = bchk_b + ks * 2;
                uint32_t rr[4];
                ldsm4(rr, bb + ((uint32_t)row << 7)
                             + (uint32_t)((ch ^ (row & 7)) << 4));
                bfr[2 * p][0]     = rr[0]; bfr[2 * p][1]     = rr[1];
                bfr[2 * p + 1][0] = rr[2]; bfr[2 * p + 1][1] = rr[3];
            }
            #pragma unroll
            for (int mt = 0; mt < 2; mt++)
                #pragma unroll
                for (int ntl = 0; ntl < 8; ntl++)
                    mma_f16(acc[mt][ntl], afr[mt], bfr[ntl]);
        }
    }

    #pragma unroll
    for (int mt = 0; mt < 2; mt++) {
        #pragma unroll
        for (int ntl = 0; ntl < 8; ntl++) {
            int row = m0 + wm * 32 + mt * 16 + g;
            int col = n0 + wn * 64 + ntl * 8 + t * 2;
            float bv0 = bias[col], bv1 = bias[col + 1];
            #pragma unroll
            for (int half_ = 0; half_ < 2; half_++) {
                int r = row + half_ * 8;
                float v0 = acc[mt][ntl][half_ * 2 + 0] + bv0;
                float v1 = acc[mt][ntl][half_ * 2 + 1] + bv1;
                if (ACT == 1) { v0 = gelu_tanh(v0); v1 = gelu_tanh(v1); }
                if (RES) {
                    float2 rr = *(const float2*)&Res[(size_t)r * ldc + col];
                    v0 += rr.x; v1 += rr.y;
                }
                if (OUTH) {
                    __half2* C = (__half2*)((__half*)Cout + (size_t)r * ldc + col);
                    *C = __floats2half2_rn(v0, v1);
                } else {
                    float* C = (float*)Cout + (size_t)r * ldc + col;
                    *(float2*)C = make_float2(v0, v1);
                }
            }
        }
    }
}

// =====================================================================
// Fused flash-attention, fp16 operands / fp32 softmax+accum (as R8).
// =====================================================================
#define ATTN_SMEM  ((128*72 + 2*64*72 + 2*64*72) * 2 + 512 * 4)   // 57344

__global__ void __launch_bounds__(256)
attn_kernel(const __half* __restrict__ qkv, const int* __restrict__ seg,
            __half* __restrict__ ctx)
{
    extern __shared__ __half hsm[];
    __half* sP    = hsm;                       // 128*72 (Q staging, then P)
    __half* sK    = sP + 128 * 72;             // 2 * 64*72
    __half* sV    = sK + 2 * 64 * 72;          // 2 * 64*72
    float*  smask = (float*)(sV + 2 * 64 * 72);

    const int bh = blockIdx.y;
    const int b = bh / NH_, h = bh - b * NH_;
    const int q0 = blockIdx.x * 128;

    const __half* qp = qkv + (size_t)b * S_ * QKVN + h * DH_;
    const __half* kp = qp + H_;
    __half* cp = ctx + ((size_t)b * S_ + q0) * H_ + h * DH_;

    const int tid = threadIdx.x, lane = tid & 31, wid = tid >> 5;
    const int g = lane >> 2, t = lane & 3;
    const uint32_t sPb = smem_u32(sP);
    const uint32_t sKb0 = smem_u32(sK);
    const uint32_t sVb0 = smem_u32(sV);

    for (int i = tid; i < S_; i += 256)
        smask[i] = (seg[b * S_ + i] > 0) ? 0.f : -1e9f;

    #pragma unroll
    for (int i = 0; i < 4; i++) {
        int c = i * 256 + tid;
        int row = c >> 3, kc = (c & 7) << 3;
        cp16s(sPb + (uint32_t)row * 144 + ((c & 7) << 4),
              qp + (size_t)(q0 + row) * QKVN + kc);
    }
    asm volatile("cp.async.commit_group;" ::: "memory");
    asm volatile("cp.async.wait_group 0;" ::: "memory");
    __syncthreads();

    const uint32_t a_base = (uint32_t)(wid * 16 + (lane & 15)) * 144 + ((lane >> 4) << 4);
    uint32_t qf[4][4];
    #pragma unroll
    for (int s = 0; s < 4; s++)
        ldsm4(qf[s], sPb + a_base + s * 32);
    __syncthreads();

    auto load_kv = [&](int kt, int buf) {
        int kbase = kt * 64;
        #pragma unroll
        for (int i = 0; i < 2; i++) {
            int c = i * 256 + tid;
            int row = c >> 3, kc = (c & 7) << 3;
            const __half* kg = kp + (size_t)(kbase + row) * QKVN + kc;
            uint32_t d = (uint32_t)row * 144 + ((c & 7) << 4);
            cp16s(sKb0 + buf * 9216 + d, kg);
            cp16s(sVb0 + buf * 9216 + d, kg + H_);
        }
        asm volatile("cp.async.commit_group;" ::: "memory");
    };
    load_kv(0, 0);

    const uint32_t bK_base = (uint32_t)(((lane >> 4) << 3) + (lane & 7)) * 144
                           + (((lane >> 3) & 1) << 4);
    const uint32_t bV_base = (uint32_t)(lane & 15) * 144 + (((lane >> 4) & 1) << 4);

    float m_run[2] = {-1e30f, -1e30f};
    float l_run[2] = {0.f, 0.f};
    float o[8][4];
    #pragma unroll
    for (int ntl = 0; ntl < 8; ntl++)
        #pragma unroll
        for (int r = 0; r < 4; r++) o[ntl][r] = 0.f;

    for (int kt = 0; kt < S_ / 64; kt++) {
        int buf = kt & 1;
        asm volatile("cp.async.wait_group 0;" ::: "memory");
        __syncthreads();
        if (kt + 1 < S_ / 64) load_kv(kt + 1, buf ^ 1);

        uint32_t sKb = sKb0 + buf * 9216;
        uint32_t sVb = sVb0 + buf * 9216;

        float sacc[8][4];
        #pragma unroll
        for (int ntl = 0; ntl < 8; ntl++)
            #pragma unroll
            for (int r = 0; r < 4; r++) sacc[ntl][r] = 0.f;
        #pragma unroll
        for (int s = 0; s < 4; s++) {
            uint32_t bfr[8][2];
            #pragma unroll
            for (int p = 0; p < 4; p++) {
                uint32_t rr[4];
                ldsm4(rr, sKb + bK_base + p * (16 * 144) + s * 32);
                bfr[2 * p][0]     = rr[0]; bfr[2 * p][1]     = rr[1];
                bfr[2 * p + 1][0] = rr[2]; bfr[2 * p + 1][1] = rr[3];
            }
            #pragma unroll
            for (int ntl = 0; ntl < 8; ntl++)
                mma_f16(sacc[ntl], qf[s], bfr[ntl]);
        }

        float tmax0 = -1e30f, tmax1 = -1e30f;
        #pragma unroll
        for (int ntl = 0; ntl < 8; ntl++) {
            int col = kt * 64 + ntl * 8 + t * 2;
            float mb0 = smask[col], mb1 = smask[col + 1];
            sacc[ntl][0] = fmaf(sacc[ntl][0], 0.125f, mb0);
            sacc[ntl][1] = fmaf(sacc[ntl][1], 0.125f, mb1);
            sacc[ntl][2] = fmaf(sacc[ntl][2], 0.125f, mb0);
            sacc[ntl][3] = fmaf(sacc[ntl][3], 0.125f, mb1);
            tmax0 = fmaxf(tmax0, fmaxf(sacc[ntl][0], sacc[ntl][1]));
            tmax1 = fmaxf(tmax1, fmaxf(sacc[ntl][2], sacc[ntl][3]));
        }
        tmax0 = fmaxf(tmax0, __shfl_xor_sync(0xffffffffu, tmax0, 1));
        tmax0 = fmaxf(tmax0, __shfl_xor_sync(0xffffffffu, tmax0, 2));
        tmax1 = fmaxf(tmax1, __shfl_xor_sync(0xffffffffu, tmax1, 1));
        tmax1 = fmaxf(tmax1, __shfl_xor_sync(0xffffffffu, tmax1, 2));
        float mnew0 = fmaxf(m_run[0], tmax0);
        float mnew1 = fmaxf(m_run[1], tmax1);
        float al0 = __expf(m_run[0] - mnew0);
        float al1 = __expf(m_run[1] - mnew1);
        float ts0 = 0.f, ts1 = 0.f;
        #pragma unroll
        for (int ntl = 0; ntl < 8; ntl++) {
            sacc[ntl][0] = __expf(sacc[ntl][0] - mnew0);
            sacc[ntl][1] = __expf(sacc[ntl][1] - mnew0);
            sacc[ntl][2] = __expf(sacc[ntl][2] - mnew1);
            sacc[ntl][3] = __expf(sacc[ntl][3] - mnew1);
            ts0 += sacc[ntl][0] + sacc[ntl][1];
            ts1 += sacc[ntl][2] + sacc[ntl][3];
        }
        ts0 += __shfl_xor_sync(0xffffffffu, ts0, 1);
        ts0 += __shfl_xor_sync(0xffffffffu, ts0, 2);
        ts1 += __shfl_xor_sync(0xffffffffu, ts1, 1);
        ts1 += __shfl_xor_sync(0xffffffffu, ts1, 2);
        l_run[0] = l_run[0] * al0 + ts0;
        l_run[1] = l_run[1] * al1 + ts1;
        m_run[0] = mnew0; m_run[1] = mnew1;
        #pragma unroll
        for (int ntl = 0; ntl < 8; ntl++) {
            o[ntl][0] *= al0; o[ntl][1] *= al0;
            o[ntl][2] *= al1; o[ntl][3] *= al1;
        }

        __half* pw = sP + (size_t)(wid * 16) * 72;
        #pragma unroll
        for (int ntl = 0; ntl < 8; ntl++) {
            int c0 = ntl * 8 + t * 2;
            *(__half2*)&pw[g * 72 + c0]       = __floats2half2_rn(sacc[ntl][0], sacc[ntl][1]);
            *(__half2*)&pw[(g + 8) * 72 + c0] = __floats2half2_rn(sacc[ntl][2], sacc[ntl][3]);
        }
        __syncwarp();
        #pragma unroll
        for (int s = 0; s < 4; s++) {
            uint32_t pf[4];
            ldsm4(pf, sPb + a_base + s * 32);
            uint32_t bfr[8][2];
            #pragma unroll
            for (int p = 0; p < 4; p++) {
                uint32_t rr[4];
                ldsm4t(rr, sVb + bV_base + s * (16 * 144) + p * 32);
                bfr[2 * p][0]     = rr[0]; bfr[2 * p][1]     = rr[1];
                bfr[2 * p + 1][0] = rr[2]; bfr[2 * p + 1][1] = rr[3];
            }
            #pragma unroll
            for (int ntl = 0; ntl < 8; ntl++)
                mma_f16(o[ntl], pf, bfr[ntl]);
        }
    }

    float rl0 = 1.f / l_run[0], rl1 = 1.f / l_run[1];
    int r0 = wid * 16 + g;
    #pragma unroll
    for (int ntl = 0; ntl < 8; ntl++) {
        int col = ntl * 8 + t * 2;
        *(__half2*)&cp[(size_t)r0 * H_ + col] =
            __floats2half2_rn(o[ntl][0] * rl0, o[ntl][1] * rl0);
        *(__half2*)&cp[(size_t)(r0 + 8) * H_ + col] =
            __floats2half2_rn(o[ntl][2] * rl1, o[ntl][3] * rl1);
    }
}

// ---------------- small SIMT GEMM (pooler + classifier only) ----------------
template<int ACT> // 0 none, 2 tanh
__global__ void gemm_kernel(const float* __restrict__ A, const float* __restrict__ Bm,
                            const float* __restrict__ bias, float* __restrict__ C,
                            int M, int N, int K, int lda, int ldb, int ldc)
{
    __shared__ float As[16][65];
    __shared__ float Bs[16][65];

    int m0 = blockIdx.y * 64;
    int n0 = blockIdx.x * 64;
    int tid = threadIdx.x;
    int tx = tid & 15, ty = tid >> 4;

    float acc[4][4] = {};

    for (int k0 = 0; k0 < K; k0 += 16) {
        #pragma unroll
        for (int i = tid; i < 64 * 16; i += 256) {
            int m = i >> 4, k = i & 15;
            int gm = m0 + m, gk = k0 + k;
            As[k][m] = (gm < M && gk < K) ? A[(long)gm * lda + gk] : 0.f;
        }
        #pragma unroll
        for (int i = tid; i < 16 * 64; i += 256) {
            int k = i >> 6, n = i & 63;
            int gk = k0 + k, gn = n0 + n;
            Bs[k][n] = (gk < K && gn < N) ? Bm[(long)gk * ldb + gn] : 0.f;
        }
        __syncthreads();
        #pragma unroll
        for (int k = 0; k < 16; k++) {
            float a[4], bb[4];
            #pragma unroll
            for (int i = 0; i < 4; i++) a[i] = As[k][ty * 4 + i];
            #pragma unroll
            for (int j = 0; j < 4; j++) bb[j] = Bs[k][tx * 4 + j];
            #pragma unroll
            for (int i = 0; i < 4; i++)
                #pragma unroll
                for (int j = 0; j < 4; j++)
                    acc[i][j] = fmaf(a[i], bb[j], acc[i][j]);
        }
        __syncthreads();
    }

    #pragma unroll
    for (int i = 0; i < 4; i++) {
        int gm = m0 + ty * 4 + i;
        if (gm >= M) continue;
        #pragma unroll
        for (int j = 0; j < 4; j++) {
            int gn = n0 + tx * 4 + j;
            if (gn >= N) continue;
            float v = acc[i][j];
            if (bias) v += bias[gn];
            if (ACT == 2) v = tanhf(v);
            C[(long)gm * ldc + gn] = v;
        }
    }
}

// ---------------- log-softmax + NLL loss + output write ----------------
__global__ void loss_kernel(const float* __restrict__ logits, const int* __restrict__ tgt,
                            float* __restrict__ out, int out_size)
{
    int lane = threadIdx.x;
    float lp = 0.f;
    if (lane < B_) {
        const float* row = logits + lane * LAB_;
        float mx = row[0];
        #pragma unroll
        for (int j = 1; j < LAB_; j++) mx = fmaxf(mx, row[j]);
        float s = 0.f;
        #pragma unroll
        for (int j = 0; j < LAB_; j++) s += expf(row[j] - mx);
        lp = row[tgt[lane]] - mx - logf(s);
    }
    #pragma unroll
    for (int o = 16; o; o >>= 1) lp += __shfl_down_sync(0xffffffffu, lp, o);
    int ofs = (out_size > B_ * LAB_) ? 1 : 0;
    if (lane == 0 && ofs) out[0] = -lp / (float)B_;
    for (int i = lane; i < B_ * LAB_; i += 32) out[ofs + i] = logits[i];
}

// ---------------- host launch ----------------
extern "C" void kernel_launch(void* const* d_in, const int* in_sizes, int n_in,
                              void* d_out, int out_size)
{
    const int*   src  = (const int*)d_in[0];
    const int*   seg  = (const int*)d_in[1];
    const int*   tgt  = (const int*)d_in[2];
    const int*   tib  = (const int*)d_in[3];
    const float* we   = (const float*)d_in[4];
    const float* pe   = (const float*)d_in[5];
    const float* se   = (const float*)d_in[6];
    const float* elng = (const float*)d_in[7];
    const float* elnb = (const float*)d_in[8];
    const float* Wq   = (const float*)d_in[9];
    const float* bq   = (const float*)d_in[10];
    const float* Wk   = (const float*)d_in[11];
    const float* bk   = (const float*)d_in[12];
    const float* Wv   = (const float*)d_in[13];
    const float* bv   = (const float*)d_in[14];
    const float* Wo   = (const float*)d_in[15];
    const float* bo   = (const float*)d_in[16];
    const float* ln1g = (const float*)d_in[17];
    const float* ln1b = (const float*)d_in[18];
    const float* Wf1  = (const float*)d_in[19];
    const float* bf1  = (const float*)d_in[20];
    const float* Wf2  = (const float*)d_in[21];
    const float* bf2  = (const float*)d_in[22];
    const float* ln2g = (const float*)d_in[23];
    const float* ln2b = (const float*)d_in[24];
    const float* Wp1  = (const float*)d_in[25];
    const float* bp1  = (const float*)d_in[26];
    const float* Wp2  = (const float*)d_in[27];
    const float* bp2  = (const float*)d_in[28];
    const float* sel  = (const float*)d_in[29];
    (void)in_sizes; (void)n_in;

    float *x, *tmp, *hidden, *logits, *bqkv;
    __half *xh, *qkv, *ctxh, *ffh, *wqkvT, *woT, *wf1T, *wf2T;
    cudaGetSymbolAddress((void**)&x,     g_x);
    cudaGetSymbolAddress((void**)&xh,    g_xh);
    cudaGetSymbolAddress((void**)&qkv,   g_qkv);
    cudaGetSymbolAddress((void**)&ctxh,  g_ctxh);
    cudaGetSymbolAddress((void**)&tmp,   g_tmp);
    cudaGetSymbolAddress((void**)&ffh,   g_ffh);
    cudaGetSymbolAddress((void**)&hidden,g_hidden);
    cudaGetSymbolAddress((void**)&logits,g_logits);
    cudaGetSymbolAddress((void**)&wqkvT, g_wqkvT);
    cudaGetSymbolAddress((void**)&woT,   g_woT);
    cudaGetSymbolAddress((void**)&wf1T,  g_wf1T);
    cudaGetSymbolAddress((void**)&wf2T,  g_wf2T);
    cudaGetSymbolAddress((void**)&bqkv,  g_bqkv);

    cudaFuncSetAttribute((const void*)hgemm<0,1,0>, cudaFuncAttributeMaxDynamicSharedMemorySize, HG_SMEM);
    cudaFuncSetAttribute((const void*)hgemm<0,0,1>, cudaFuncAttributeMaxDynamicSharedMemorySize, HG_SMEM);
    cudaFuncSetAttribute((const void*)hgemm<1,1,0>, cudaFuncAttributeMaxDynamicSharedMemorySize, HG_SMEM);
    cudaFuncSetAttribute((const void*)attn_kernel,  cudaFuncAttributeMaxDynamicSharedMemorySize, ATTN_SMEM);

    const int Mtok = B_ * S_;                    // 8192

    // weight prep
    {
        dim3 tb(32, 8);
        dim3 gHH(H_ / 32, H_ / 32, L_);
        transpose_cvt<<<gHH, tb>>>(Wq, wqkvT,                   H_, H_, (long)QKVN * H_);
        transpose_cvt<<<gHH, tb>>>(Wk, wqkvT + (size_t)H_*H_,   H_, H_, (long)QKVN * H_);
        transpose_cvt<<<gHH, tb>>>(Wv, wqkvT + (size_t)2*H_*H_, H_, H_, (long)QKVN * H_);
        transpose_cvt<<<gHH, tb>>>(Wo, woT, H_, H_, (long)H_ * H_);
        dim3 gF1(FF_ / 32, H_ / 32, L_);
        transpose_cvt<<<gF1, tb>>>(Wf1, wf1T, H_, FF_, (long)FF_ * H_);
        dim3 gF2(H_ / 32, FF_ / 32, L_);
        transpose_cvt<<<gF2, tb>>>(Wf2, wf2T, FF_, H_, (long)H_ * FF_);
        concat_bias<<<(L_ * QKVN + 255) / 256, 256>>>(bq, bk, bv, bqkv);
    }

    embed_kernel<<<Mtok / 8, 256>>>(src, seg, tib, we, pe, se, elng, elnb, sel, x, xh);

    dim3 gQKV(QKVN / 128, Mtok / 128);   // (18, 64)
    dim3 gH  (H_   / 128, Mtok / 128);   // (6, 64)
    dim3 gFF (FF_  / 128, Mtok / 128);   // (24, 64)
    dim3 gAtt(S_ / 128, B_ * NH_);       // (4, 192)

    for (int l = 0; l < L_; l++) {
        const __half* wqkv = wqkvT + (size_t)l * QKVN * H_;
        const __half* wo   = woT   + (size_t)l * H_ * H_;
        const __half* wf1  = wf1T  + (size_t)l * H_ * FF_;
        const __half* wf2  = wf2T  + (size_t)l * FF_ * H_;

        hgemm<0,1,0><<<gQKV, 256, HG_SMEM>>>(xh, wqkv, bqkv + l * QKVN, qkv, nullptr,
                                             H_, H_, H_, QKVN);
        attn_kernel<<<gAtt, 256, ATTN_SMEM>>>(qkv, seg, ctxh);
        // tmp = ctx @ Wo + bo + x  (residual fused)
        hgemm<0,0,1><<<gH, 256, HG_SMEM>>>(ctxh, wo, bo + l * H_, tmp, x,
                                           H_, H_, H_, H_);
        ln_kernel<<<Mtok / 8, 256>>>(tmp, ln1g + l * H_, ln1b + l * H_, x, xh);

        hgemm<1,1,0><<<gFF, 256, HG_SMEM>>>(xh, wf1, bf1 + l * FF_, ffh, nullptr,
                                            H_, H_, H_, FF_);
        // tmp = gelu_ff @ Wf2 + bf2 + x  (residual fused)
        hgemm<0,0,1><<<gH, 256, HG_SMEM>>>(ffh, wf2, bf2 + l * H_, tmp, x,
                                           FF_, FF_, FF_, H_);
        ln_kernel<<<Mtok / 8, 256>>>(tmp, ln2g + l * H_, ln2b + l * H_, x, xh);
    }

    dim3 gPool((H_ + 63) / 64, 1);
    gemm_kernel<2><<<gPool, 256>>>(x, Wp1, bp1, hidden, B_, H_, H_,
                                   S_ * H_, H_, H_);
    dim3 gCls(1, 1);
    gemm_kernel<0><<<gCls, 256>>>(hidden, Wp2, bp2, logits, B_, LAB_, H_,
                                  H_, LAB_, LAB_);

    loss_kernel<<<1, 32>>>(logits, tgt, (float*)d_out, out_size);
}